// round 12
// baseline (speedup 1.0000x reference)
#include <cuda_runtime.h>
#include <cuda_bf16.h>
#include <math.h>
#include <stdint.h>

#define DMODEL 1024
#define NHEAD  16
#define FFDIM  4096
#define ROWS   4096      // B*S
#define SEQ    2048
#define QKVW   3072      // packed qkv width
#define LN_EPS 1e-6f

typedef __nv_bfloat16 bf16;

// ---------------- scratch (no allocation allowed) ----------------
__device__ float g_x1[ROWS * DMODEL];

__device__ bf16 g_lnh  [ROWS * DMODEL],   g_lnl  [ROWS * DMODEL];
__device__ bf16 g_qkvh [ROWS * QKVW],     g_qkvl [ROWS * QKVW];    // [row][q|k|v]
__device__ bf16 g_vth  [ROWS * DMODEL],   g_vtl  [ROWS * DMODEL];  // [b,h,d,s]
__device__ bf16 g_atth [ROWS * DMODEL],   g_attl [ROWS * DMODEL];
__device__ bf16 g_ffh  [ROWS * FFDIM],    g_ffl  [ROWS * FFDIM];
__device__ bf16 g_wqkvh[QKVW * DMODEL],   g_wqkvl[QKVW * DMODEL];  // [n][k]
__device__ bf16 g_woh  [DMODEL * DMODEL], g_wol  [DMODEL * DMODEL];
__device__ bf16 g_w1h  [DMODEL * FFDIM],  g_w1l  [DMODEL * FFDIM];
__device__ bf16 g_w2h  [FFDIM * DMODEL],  g_w2l  [FFDIM * DMODEL];

__device__ __forceinline__ void split2(float f, bf16& h, bf16& l) {
    h = __float2bfloat16_rn(f);
    l = __float2bfloat16_rn(f - __bfloat162float(h));
}
__device__ __forceinline__ unsigned packbf2(float a, float b) {
    __nv_bfloat162 t;
    t.x = __float2bfloat16_rn(a);
    t.y = __float2bfloat16_rn(b);
    return *(unsigned*)&t;
}
__device__ __forceinline__ unsigned packlo2(float a, float b) {
    __nv_bfloat162 t;
    t.x = __float2bfloat16_rn(a - __bfloat162float(__float2bfloat16_rn(a)));
    t.y = __float2bfloat16_rn(b - __bfloat162float(__float2bfloat16_rn(b)));
    return *(unsigned*)&t;
}

// ---------------- LayerNorm -> bf16 hi/lo split output ----------------
__global__ void ln_split_kernel(const float* __restrict__ x,
                                const float* __restrict__ gamma,
                                const float* __restrict__ beta,
                                bf16* __restrict__ oh, bf16* __restrict__ ol) {
    int row = blockIdx.x;
    int t = threadIdx.x;
    const float4* xr = (const float4*)(x + (size_t)row * DMODEL);
    float4 v = xr[t];
    float s  = v.x + v.y + v.z + v.w;
    float ss = v.x * v.x + v.y * v.y + v.z * v.z + v.w * v.w;
    #pragma unroll
    for (int o = 16; o > 0; o >>= 1) {
        s  += __shfl_xor_sync(0xFFFFFFFFu, s,  o);
        ss += __shfl_xor_sync(0xFFFFFFFFu, ss, o);
    }
    __shared__ float rs[8], rss[8];
    int wid = t >> 5, lid = t & 31;
    if (lid == 0) { rs[wid] = s; rss[wid] = ss; }
    __syncthreads();
    s = 0.f; ss = 0.f;
    #pragma unroll
    for (int i = 0; i < 8; i++) { s += rs[i]; ss += rss[i]; }
    float mean = s * (1.0f / DMODEL);
    float var  = (ss - (float)DMODEL * mean * mean) * (1.0f / (DMODEL - 1));
    float inv  = 1.0f / (sqrtf(fmaxf(var, 0.0f)) + LN_EPS);
    const float4 gg = ((const float4*)gamma)[t];
    const float4 bb = ((const float4*)beta)[t];
    float o4[4];
    o4[0] = gg.x * (v.x - mean) * inv + bb.x;
    o4[1] = gg.y * (v.y - mean) * inv + bb.y;
    o4[2] = gg.z * (v.z - mean) * inv + bb.z;
    o4[3] = gg.w * (v.w - mean) * inv + bb.w;
    bf16 hh[4], ll[4];
    #pragma unroll
    for (int j = 0; j < 4; j++) split2(o4[j], hh[j], ll[j]);
    size_t base = (size_t)row * DMODEL + t * 4;
    *(uint2*)(oh + base) = *(uint2*)hh;
    *(uint2*)(ol + base) = *(uint2*)ll;
}

// ---------------- Weight transpose + split: [K,N] fp32 -> [N][K] bf16 hi/lo ----
__global__ void wsplit_tr_kernel(const float* __restrict__ W,
                                 bf16* __restrict__ Th, bf16* __restrict__ Tl,
                                 int K, int N) {
    __shared__ float t[32][33];
    int n0 = blockIdx.x * 32, k0 = blockIdx.y * 32;
    int tx = threadIdx.x, ty = threadIdx.y;   // 32 x 8
    #pragma unroll
    for (int i = 0; i < 4; i++)
        t[ty + 8 * i][tx] = W[(size_t)(k0 + ty + 8 * i) * N + n0 + tx];
    __syncthreads();
    #pragma unroll
    for (int i = 0; i < 4; i++) {
        float f = t[tx][ty + 8 * i];
        bf16 h, l; split2(f, h, l);
        size_t o = (size_t)(n0 + ty + 8 * i) * K + k0 + tx;
        Th[o] = h; Tl[o] = l;
    }
}

// ---------------- V transpose: packed qkv [row][3072] col 2048+ -> [b,h,d,s] ----
__global__ void vtr_kernel(const bf16* __restrict__ V, bf16* __restrict__ Vt) {
    __shared__ bf16 t[32][33];
    int s0 = blockIdx.x * 32, d0 = blockIdx.y * 32, z = blockIdx.z;  // z = b*16+h
    int bq = z >> 4, hq = z & 15;
    int tx = threadIdx.x, ty = threadIdx.y;    // 32 x 8
    #pragma unroll
    for (int i = 0; i < 4; i++)
        t[ty + 8 * i][tx] = V[(size_t)(bq * SEQ + s0 + ty + 8 * i) * QKVW + 2048 + hq * 64 + d0 + tx];
    __syncthreads();
    #pragma unroll
    for (int i = 0; i < 4; i++)
        Vt[(size_t)(z * 64 + d0 + ty + 8 * i) * SEQ + s0 + tx] = t[tx][ty + 8 * i];
}

// ---------------- common helpers ----------------
__device__ __forceinline__ void cpa16(uint32_t d, const void* s) {
    asm volatile("cp.async.cg.shared.global [%0], [%1], 16;" :: "r"(d), "l"(s));
}
__device__ __forceinline__ void cpcommit() {
    asm volatile("cp.async.commit_group;");
}
template<int W> __device__ __forceinline__ void cpwait() {
    asm volatile("cp.async.wait_group %0;" :: "n"(W));
}
__device__ __forceinline__ void mma16816(float c[4], const unsigned a[4], const unsigned b[2]) {
    asm volatile(
        "mma.sync.aligned.m16n8k16.row.col.f32.bf16.bf16.f32 "
        "{%0,%1,%2,%3}, {%4,%5,%6,%7}, {%8,%9}, {%0,%1,%2,%3};\n"
        : "+f"(c[0]), "+f"(c[1]), "+f"(c[2]), "+f"(c[3])
        : "r"(a[0]), "r"(a[1]), "r"(a[2]), "r"(a[3]), "r"(b[0]), "r"(b[1]));
}

// ---------------- Tensor-core GEMM: R6 tile/pipeline, 512 threads (4x4 warps) ----
// A(hi/lo): [M][K] bf16 rm. B(hi/lo): [N][K] bf16 (k-contiguous). C = act(A@B^T)+res.
#define BM 128
#define BN 128
#define BK 32
#define SKP 40
#define TILE_B (128 * SKP * 2)      // 10240 B
#define STAGE_B (4 * TILE_B)        // 40960 B
#define GTHR 512

__device__ __forceinline__ void fill_stage(uint32_t sb,
        const bf16* __restrict__ Agh, const bf16* __restrict__ Agl,
        const bf16* __restrict__ Bgh, const bf16* __restrict__ Bgl,
        int row0, int col0, int k0, int K, int tid) {
    int r  = tid >> 2;                 // 0..127
    int kb = (tid & 3) * 16;           // 16B chunk within 64B of k-data
    size_t aoff = ((size_t)(row0 + r) * K + k0) * 2 + kb;
    size_t boff = ((size_t)(col0 + r) * K + k0) * 2 + kb;
    uint32_t dst = sb + (uint32_t)r * (SKP * 2) + kb;
    cpa16(dst,              (const char*)Agh + aoff);
    cpa16(dst + TILE_B,     (const char*)Agl + aoff);
    cpa16(dst + 2 * TILE_B, (const char*)Bgh + boff);
    cpa16(dst + 3 * TILE_B, (const char*)Bgl + boff);
}

template<bool RELU, bool SPLIT>
__global__ __launch_bounds__(GTHR)
void gemm_mma(const bf16* __restrict__ Agh, const bf16* __restrict__ Agl,
              const bf16* __restrict__ Bgh, const bf16* __restrict__ Bgl,
              const float* __restrict__ bias, const float* __restrict__ res,
              float* __restrict__ C, bf16* __restrict__ Ch, bf16* __restrict__ Cl,
              int M, int N, int K) {
    extern __shared__ bf16 smem[];
    uint32_t sbase = (uint32_t)__cvta_generic_to_shared(smem);
    int tid = threadIdx.x, lane = tid & 31, warp = tid >> 5;   // 16 warps
    int g = lane >> 2, tig = lane & 3;
    int m_base = (warp & 3) * 32, n_base = (warp >> 2) * 32;   // 4x4 warp grid
    int row0 = blockIdx.y * BM, col0 = blockIdx.x * BN;

    float acc[2][4][4];
    #pragma unroll
    for (int mi = 0; mi < 2; mi++)
        #pragma unroll
        for (int ni = 0; ni < 4; ni++)
            #pragma unroll
            for (int r = 0; r < 4; r++) acc[mi][ni][r] = 0.0f;

    int NIT = K >> 5;
    fill_stage(sbase, Agh, Agl, Bgh, Bgl, row0, col0, 0, K, tid);
    cpcommit();

    for (int it = 0; it < NIT; ++it) {
        if (it + 1 < NIT) {
            fill_stage(sbase + ((it + 1) & 1) * STAGE_B, Agh, Agl, Bgh, Bgl,
                       row0, col0, (it + 1) << 5, K, tid);
            cpcommit();
            cpwait<1>();
        } else {
            cpwait<0>();
        }
        __syncthreads();

        const bf16* st  = smem + (it & 1) * (STAGE_B / 2);
        const bf16* Ahs = st;
        const bf16* Als = st + TILE_B / 2;
        const bf16* Bhs = st + 2 * (TILE_B / 2);
        const bf16* Bls = st + 3 * (TILE_B / 2);

        #pragma unroll
        for (int ks = 0; ks < 2; ks++) {
            int kk = ks * 16;
            unsigned a_h[2][4], a_l[2][4], b_h[4][2], b_l[4][2];
            #pragma unroll
            for (int mi = 0; mi < 2; mi++) {
                int r = m_base + mi * 16 + g;
                int base = r * SKP + kk + 2 * tig;
                a_h[mi][0] = *(const unsigned*)(Ahs + base);
                a_h[mi][1] = *(const unsigned*)(Ahs + base + 8 * SKP);
                a_h[mi][2] = *(const unsigned*)(Ahs + base + 8);
                a_h[mi][3] = *(const unsigned*)(Ahs + base + 8 * SKP + 8);
                a_l[mi][0] = *(const unsigned*)(Als + base);
                a_l[mi][1] = *(const unsigned*)(Als + base + 8 * SKP);
                a_l[mi][2] = *(const unsigned*)(Als + base + 8);
                a_l[mi][3] = *(const unsigned*)(Als + base + 8 * SKP + 8);
            }
            #pragma unroll
            for (int ni = 0; ni < 4; ni++) {
                int n = n_base + ni * 8 + g;
                int base = n * SKP + kk + 2 * tig;
                b_h[ni][0] = *(const unsigned*)(Bhs + base);
                b_h[ni][1] = *(const unsigned*)(Bhs + base + 8);
                b_l[ni][0] = *(const unsigned*)(Bls + base);
                b_l[ni][1] = *(const unsigned*)(Bls + base + 8);
            }
            #pragma unroll
            for (int mi = 0; mi < 2; mi++)
                #pragma unroll
                for (int ni = 0; ni < 4; ni++) {
                    mma16816(acc[mi][ni], a_h[mi], b_h[ni]);
                    mma16816(acc[mi][ni], a_h[mi], b_l[ni]);
                    mma16816(acc[mi][ni], a_l[mi], b_h[ni]);
                }
        }
        __syncthreads();
    }

    #pragma unroll
    for (int mi = 0; mi < 2; mi++) {
        #pragma unroll
        for (int ni = 0; ni < 4; ni++) {
            int r = row0 + m_base + mi * 16 + g;
            int c = col0 + n_base + ni * 8 + 2 * tig;
            float2 b2 = make_float2(0.f, 0.f);
            if (bias) b2 = *(const float2*)(bias + c);
            float2 v0, v1;
            v0.x = acc[mi][ni][0] + b2.x; v0.y = acc[mi][ni][1] + b2.y;
            v1.x = acc[mi][ni][2] + b2.x; v1.y = acc[mi][ni][3] + b2.y;
            if (RELU) {
                v0.x = fmaxf(v0.x, 0.f); v0.y = fmaxf(v0.y, 0.f);
                v1.x = fmaxf(v1.x, 0.f); v1.y = fmaxf(v1.y, 0.f);
            }
            if (res) {
                float2 r0 = *(const float2*)(res + (size_t)r * N + c);
                float2 r1 = *(const float2*)(res + (size_t)(r + 8) * N + c);
                v0.x += r0.x; v0.y += r0.y; v1.x += r1.x; v1.y += r1.y;
            }
            if (SPLIT) {
                *(unsigned*)(Ch + (size_t)r * N + c)       = packbf2(v0.x, v0.y);
                *(unsigned*)(Ch + (size_t)(r + 8) * N + c) = packbf2(v1.x, v1.y);
                *(unsigned*)(Cl + (size_t)r * N + c)       = packlo2(v0.x, v0.y);
                *(unsigned*)(Cl + (size_t)(r + 8) * N + c) = packlo2(v1.x, v1.y);
            } else {
                *(float2*)(C + (size_t)r * N + c)       = v0;
                *(float2*)(C + (size_t)(r + 8) * N + c) = v1;
            }
        }
    }
}

// ---------------- MMA flash attention (R6 structure; packed QKV input) ----------
#define AQT 128
#define ASK 72
#define AROWB (ASK * 2)
#define ATILE (64 * AROWB)
#define ASTAGE (4 * ATILE)

__device__ __forceinline__ void attn_fill(uint32_t sb, int stage,
        const bf16* __restrict__ QKVh, const bf16* __restrict__ QKVl,
        const bf16* __restrict__ Vth, const bf16* __restrict__ Vtl,
        int b, int h, int kt, int tid) {
    int r  = tid >> 2;
    int q4 = (tid & 3) * 32;
    size_t koff = ((size_t)(b * SEQ + kt * 64 + r) * QKVW + 1024 + h * 64) * 2 + q4;
    size_t voff = ((size_t)((b * NHEAD + h) * 64 + r) * SEQ + kt * 64) * 2 + q4;
    uint32_t d = sb + stage * ASTAGE + (uint32_t)r * AROWB + q4;
    cpa16(d,                  (const char*)QKVh + koff);
    cpa16(d + 16,             (const char*)QKVh + koff + 16);
    cpa16(d + ATILE,          (const char*)QKVl + koff);
    cpa16(d + ATILE + 16,     (const char*)QKVl + koff + 16);
    cpa16(d + 2 * ATILE,      (const char*)Vth + voff);
    cpa16(d + 2 * ATILE + 16, (const char*)Vth + voff + 16);
    cpa16(d + 3 * ATILE,      (const char*)Vtl + voff);
    cpa16(d + 3 * ATILE + 16, (const char*)Vtl + voff + 16);
}

__global__ __launch_bounds__(256)
void attn_mma_kernel(const bf16* __restrict__ QKVh, const bf16* __restrict__ QKVl,
                     const bf16* __restrict__ Vth, const bf16* __restrict__ Vtl,
                     bf16* __restrict__ Oh, bf16* __restrict__ Ol) {
    extern __shared__ char smraw[];
    uint32_t sb = (uint32_t)__cvta_generic_to_shared(smraw);
    int b = blockIdx.z, h = blockIdx.y, qb = blockIdx.x * AQT;
    int tid = threadIdx.x, lane = tid & 31, warp = tid >> 5;
    int g = lane >> 2, tig = lane & 3;

    {   // stage Q tile (128 x 64) hi/lo from packed cols [0,1024)
        int r = tid >> 1;
        int half = (tid & 1) * 64;
        size_t qoff = ((size_t)(b * SEQ + qb + r) * QKVW + h * 64) * 2 + half;
        uint32_t d0 = sb + (uint32_t)r * AROWB + half;
        #pragma unroll
        for (int i = 0; i < 4; i++) cpa16(d0 + 16 * i, (const char*)QKVh + qoff + 16 * i);
        uint32_t d1 = sb + 2 * ATILE + (uint32_t)r * AROWB + half;
        #pragma unroll
        for (int i = 0; i < 4; i++) cpa16(d1 + 16 * i, (const char*)QKVl + qoff + 16 * i);
    }
    cpcommit(); cpwait<0>(); __syncthreads();

    unsigned qfh[4][4], qfl[4][4];
    {
        const bf16* Qs_h = (const bf16*)smraw;
        const bf16* Qs_l = (const bf16*)(smraw + 2 * ATILE);
        int mrow = warp * 16 + g;
        #pragma unroll
        for (int ks = 0; ks < 4; ks++) {
            int base = mrow * ASK + ks * 16 + 2 * tig;
            qfh[ks][0] = *(const unsigned*)(Qs_h + base);
            qfh[ks][1] = *(const unsigned*)(Qs_h + base + 8 * ASK);
            qfh[ks][2] = *(const unsigned*)(Qs_h + base + 8);
            qfh[ks][3] = *(const unsigned*)(Qs_h + base + 8 * ASK + 8);
            qfl[ks][0] = *(const unsigned*)(Qs_l + base);
            qfl[ks][1] = *(const unsigned*)(Qs_l + base + 8 * ASK);
            qfl[ks][2] = *(const unsigned*)(Qs_l + base + 8);
            qfl[ks][3] = *(const unsigned*)(Qs_l + base + 8 * ASK + 8);
        }
    }
    __syncthreads();

    float oacc[8][4];
    #pragma unroll
    for (int nf = 0; nf < 8; nf++)
        #pragma unroll
        for (int c = 0; c < 4; c++) oacc[nf][c] = 0.f;
    float mrow[2] = {-1e30f, -1e30f}, lrow[2] = {0.f, 0.f};

    const int NKT = SEQ / 64;
    attn_fill(sb, 0, QKVh, QKVl, Vth, Vtl, b, h, 0, tid);
    cpcommit();

    for (int kt = 0; kt < NKT; kt++) {
        if (kt + 1 < NKT) {
            attn_fill(sb, (kt + 1) & 1, QKVh, QKVl, Vth, Vtl, b, h, kt + 1, tid);
            cpcommit();
            cpwait<1>();
        } else {
            cpwait<0>();
        }
        __syncthreads();

        const bf16* st   = (const bf16*)(smraw + (kt & 1) * ASTAGE);
        const bf16* Ks_h = st;
        const bf16* Ks_l = st + ATILE / 2;
        const bf16* Vs_h = st + 2 * (ATILE / 2);
        const bf16* Vs_l = st + 3 * (ATILE / 2);

        float sacc[8][4];
        #pragma unroll
        for (int nf = 0; nf < 8; nf++)
            #pragma unroll
            for (int c = 0; c < 4; c++) sacc[nf][c] = 0.f;
        #pragma unroll
        for (int ks = 0; ks < 4; ks++) {
            #pragma unroll
            for (int nf = 0; nf < 8; nf++) {
                int n = nf * 8 + g;
                int base = n * ASK + ks * 16 + 2 * tig;
                unsigned bh2[2], bl2[2];
                bh2[0] = *(const unsigned*)(Ks_h + base);
                bh2[1] = *(const unsigned*)(Ks_h + base + 8);
                bl2[0] = *(const unsigned*)(Ks_l + base);
                bl2[1] = *(const unsigned*)(Ks_l + base + 8);
                mma16816(sacc[nf], qfh[ks], bh2);
                mma16816(sacc[nf], qfh[ks], bl2);
                mma16816(sacc[nf], qfl[ks], bh2);
            }
        }

        #pragma unroll
        for (int nf = 0; nf < 8; nf++)
            #pragma unroll
            for (int c = 0; c < 4; c++) sacc[nf][c] *= 0.125f;

        #pragma unroll
        for (int rr = 0; rr < 2; rr++) {
            float rm = -1e30f;
            #pragma unroll
            for (int nf = 0; nf < 8; nf++)
                rm = fmaxf(rm, fmaxf(sacc[nf][2 * rr], sacc[nf][2 * rr + 1]));
            rm = fmaxf(rm, __shfl_xor_sync(0xFFFFFFFFu, rm, 1));
            rm = fmaxf(rm, __shfl_xor_sync(0xFFFFFFFFu, rm, 2));
            float mn = fmaxf(mrow[rr], rm);
            float al = __expf(mrow[rr] - mn);
            mrow[rr] = mn;
            float rs = 0.f;
            #pragma unroll
            for (int nf = 0; nf < 8; nf++) {
                sacc[nf][2 * rr]     = __expf(sacc[nf][2 * rr]     - mn);
                sacc[nf][2 * rr + 1] = __expf(sacc[nf][2 * rr + 1] - mn);
                rs += sacc[nf][2 * rr] + sacc[nf][2 * rr + 1];
            }
            rs += __shfl_xor_sync(0xFFFFFFFFu, rs, 1);
            rs += __shfl_xor_sync(0xFFFFFFFFu, rs, 2);
            lrow[rr] = lrow[rr] * al + rs;
            #pragma unroll
            for (int nf = 0; nf < 8; nf++) {
                oacc[nf][2 * rr]     *= al;
                oacc[nf][2 * rr + 1] *= al;
            }
        }

        #pragma unroll
        for (int ks = 0; ks < 4; ks++) {
            unsigned ph2[4], pl2[4];
            ph2[0] = packbf2(sacc[2 * ks][0],     sacc[2 * ks][1]);
            ph2[1] = packbf2(sacc[2 * ks][2],     sacc[2 * ks][3]);
            ph2[2] = packbf2(sacc[2 * ks + 1][0], sacc[2 * ks + 1][1]);
            ph2[3] = packbf2(sacc[2 * ks + 1][2], sacc[2 * ks + 1][3]);
            pl2[0] = packlo2(sacc[2 * ks][0],     sacc[2 * ks][1]);
            pl2[1] = packlo2(sacc[2 * ks][2],     sacc[2 * ks][3]);
            pl2[2] = packlo2(sacc[2 * ks + 1][0], sacc[2 * ks + 1][1]);
            pl2[3] = packlo2(sacc[2 * ks + 1][2], sacc[2 * ks + 1][3]);
            #pragma unroll
            for (int nf = 0; nf < 8; nf++) {
                int n = nf * 8 + g;
                int base = n * ASK + ks * 16 + 2 * tig;
                unsigned vh2[2], vl2[2];
                vh2[0] = *(const unsigned*)(Vs_h + base);
                vh2[1] = *(const unsigned*)(Vs_h + base + 8);
                vl2[0] = *(const unsigned*)(Vs_l + base);
                vl2[1] = *(const unsigned*)(Vs_l + base + 8);
                mma16816(oacc[nf], ph2, vh2);
                mma16816(oacc[nf], ph2, vl2);
                mma16816(oacc[nf], pl2, vh2);
            }
        }
        __syncthreads();
    }

    #pragma unroll
    for (int rr = 0; rr < 2; rr++) {
        float inv = 1.0f / lrow[rr];
        size_t r_glob = (size_t)(b * SEQ + qb + warp * 16 + g + rr * 8);
        #pragma unroll
        for (int nf = 0; nf < 8; nf++) {
            int col = h * 64 + nf * 8 + 2 * tig;
            float o0 = oacc[nf][2 * rr] * inv;
            float o1 = oacc[nf][2 * rr + 1] * inv;
            *(unsigned*)(Oh + r_glob * DMODEL + col) = packbf2(o0, o1);
            *(unsigned*)(Ol + r_glob * DMODEL + col) = packlo2(o0, o1);
        }
    }
}

// ---------------- launch ----------------
extern "C" void kernel_launch(void* const* d_in, const int* in_sizes, int n_in,
                              void* d_out, int out_size) {
    const float* x   = (const float*)d_in[0];
    const float* w_q = (const float*)d_in[1];
    const float* w_k = (const float*)d_in[2];
    const float* w_v = (const float*)d_in[3];
    const float* w_o = (const float*)d_in[4];
    const float* w1  = (const float*)d_in[5];
    const float* b1  = (const float*)d_in[6];
    const float* w2  = (const float*)d_in[7];
    const float* b2  = (const float*)d_in[8];
    const float* g1  = (const float*)d_in[9];
    const float* be1 = (const float*)d_in[10];
    const float* g2  = (const float*)d_in[11];
    const float* be2 = (const float*)d_in[12];
    float* out = (float*)d_out;

    float *x1;
    bf16 *lnh, *lnl, *qkvh, *qkvl, *vth, *vtl, *atth, *attl, *ffh, *ffl;
    bf16 *wqkvh, *wqkvl, *woh, *wol, *w1h, *w1l, *w2h, *w2l;
    cudaGetSymbolAddress((void**)&x1,    g_x1);
    cudaGetSymbolAddress((void**)&lnh,   g_lnh);   cudaGetSymbolAddress((void**)&lnl,   g_lnl);
    cudaGetSymbolAddress((void**)&qkvh,  g_qkvh);  cudaGetSymbolAddress((void**)&qkvl,  g_qkvl);
    cudaGetSymbolAddress((void**)&vth,   g_vth);   cudaGetSymbolAddress((void**)&vtl,   g_vtl);
    cudaGetSymbolAddress((void**)&atth,  g_atth);  cudaGetSymbolAddress((void**)&attl,  g_attl);
    cudaGetSymbolAddress((void**)&ffh,   g_ffh);   cudaGetSymbolAddress((void**)&ffl,   g_ffl);
    cudaGetSymbolAddress((void**)&wqkvh, g_wqkvh); cudaGetSymbolAddress((void**)&wqkvl, g_wqkvl);
    cudaGetSymbolAddress((void**)&woh,   g_woh);   cudaGetSymbolAddress((void**)&wol,   g_wol);
    cudaGetSymbolAddress((void**)&w1h,   g_w1h);   cudaGetSymbolAddress((void**)&w1l,   g_w1l);
    cudaGetSymbolAddress((void**)&w2h,   g_w2h);   cudaGetSymbolAddress((void**)&w2l,   g_w2l);

    const int gemm_smem = 2 * STAGE_B;   // 81920 B
    cudaFuncSetAttribute(gemm_mma<false, false>, cudaFuncAttributeMaxDynamicSharedMemorySize, gemm_smem);
    cudaFuncSetAttribute(gemm_mma<false, true >, cudaFuncAttributeMaxDynamicSharedMemorySize, gemm_smem);
    cudaFuncSetAttribute(gemm_mma<true,  true >, cudaFuncAttributeMaxDynamicSharedMemorySize, gemm_smem);
    const int attn_smem = 2 * ASTAGE;
    cudaFuncSetAttribute(attn_mma_kernel, cudaFuncAttributeMaxDynamicSharedMemorySize, attn_smem);

    dim3 wb(32, 8);
    dim3 gQKV (QKVW / BN, ROWS / BM);    // 24 x 32 = 768 CTAs
    dim3 gProj(DMODEL / BN, ROWS / BM);  // 8 x 32
    dim3 gFF1 (FFDIM / BN, ROWS / BM);   // 32 x 32

    // launch 0: LN1
    ln_split_kernel<<<ROWS, 256>>>(x, g1, be1, lnh, lnl);
    // launches 1-4: weight splits needed before QKV gemm
    wsplit_tr_kernel<<<dim3(DMODEL/32, DMODEL/32), wb>>>(w_q, wqkvh,                 wqkvl,                 DMODEL, DMODEL);
    wsplit_tr_kernel<<<dim3(DMODEL/32, DMODEL/32), wb>>>(w_k, wqkvh + 1024 * DMODEL, wqkvl + 1024 * DMODEL, DMODEL, DMODEL);
    wsplit_tr_kernel<<<dim3(DMODEL/32, DMODEL/32), wb>>>(w_v, wqkvh + 2048 * DMODEL, wqkvl + 2048 * DMODEL, DMODEL, DMODEL);
    wsplit_tr_kernel<<<dim3(DMODEL/32, DMODEL/32), wb>>>(w_o, woh, wol, DMODEL, DMODEL);
    // launch 5: fused QKV GEMM (512 threads)
    gemm_mma<false,true><<<gQKV, GTHR, gemm_smem>>>(lnh, lnl, wqkvh, wqkvl, nullptr, nullptr, nullptr, qkvh, qkvl, ROWS, QKVW, DMODEL);
    // remaining weight preps
    wsplit_tr_kernel<<<dim3(FFDIM/32,  DMODEL/32), wb>>>(w1, w1h, w1l, DMODEL, FFDIM);
    wsplit_tr_kernel<<<dim3(DMODEL/32, FFDIM/32),  wb>>>(w2, w2h, w2l, FFDIM, DMODEL);
    // V transpose to [b,h,d,s] (reads packed v block)
    vtr_kernel<<<dim3(SEQ/32, 2, 32), wb>>>(qkvh, vth);
    vtr_kernel<<<dim3(SEQ/32, 2, 32), wb>>>(qkvl, vtl);
    // MMA attention -> split output
    attn_mma_kernel<<<dim3(SEQ/AQT, NHEAD, 2), 256, attn_smem>>>(qkvh, qkvl, vth, vtl, atth, attl);
    // output projection + residual (fp32 out)
    gemm_mma<false,false><<<gProj, GTHR, gemm_smem>>>(atth, attl, woh, wol, nullptr, x, x1, nullptr, nullptr, ROWS, DMODEL, DMODEL);
    // LN2 -> split
    ln_split_kernel<<<ROWS, 256>>>(x1, g2, be2, lnh, lnl);
    // FFN
    gemm_mma<true, true ><<<gFF1,  GTHR, gemm_smem>>>(lnh, lnl, w1h, w1l, b1, nullptr, nullptr, ffh, ffl, ROWS, FFDIM, DMODEL);
    gemm_mma<false,false><<<gProj, GTHR, gemm_smem>>>(ffh, ffl, w2h, w2l, b2, x1, out, nullptr, nullptr, ROWS, DMODEL, FFDIM);
}

// round 15
// speedup vs baseline: 1.0545x; 1.0545x over previous
#include <cuda_runtime.h>
#include <cuda_bf16.h>
#include <math.h>
#include <stdint.h>

#define DMODEL 1024
#define NHEAD  16
#define FFDIM  4096
#define ROWS   4096      // B*S
#define SEQ    2048
#define QKVW   3072      // packed qkv width
#define LN_EPS 1e-6f

typedef __nv_bfloat16 bf16;

// ---------------- scratch (no allocation allowed) ----------------
__device__ float g_x1[ROWS * DMODEL];

__device__ bf16 g_lnh  [ROWS * DMODEL],   g_lnl  [ROWS * DMODEL];
__device__ bf16 g_qkvh [ROWS * QKVW],     g_qkvl [ROWS * QKVW];    // [row][q|k|v]
__device__ bf16 g_vth  [ROWS * DMODEL],   g_vtl  [ROWS * DMODEL];  // [b,h,d,s]
__device__ bf16 g_atth [ROWS * DMODEL],   g_attl [ROWS * DMODEL];
__device__ bf16 g_ffh  [ROWS * FFDIM],    g_ffl  [ROWS * FFDIM];
__device__ bf16 g_wqkvh[QKVW * DMODEL],   g_wqkvl[QKVW * DMODEL];  // [n][k]
__device__ bf16 g_woh  [DMODEL * DMODEL], g_wol  [DMODEL * DMODEL];
__device__ bf16 g_w1h  [DMODEL * FFDIM],  g_w1l  [DMODEL * FFDIM];
__device__ bf16 g_w2h  [FFDIM * DMODEL],  g_w2l  [FFDIM * DMODEL];

__device__ __forceinline__ void split2(float f, bf16& h, bf16& l) {
    h = __float2bfloat16_rn(f);
    l = __float2bfloat16_rn(f - __bfloat162float(h));
}
__device__ __forceinline__ unsigned packbf2(float a, float b) {
    __nv_bfloat162 t;
    t.x = __float2bfloat16_rn(a);
    t.y = __float2bfloat16_rn(b);
    return *(unsigned*)&t;
}
__device__ __forceinline__ unsigned packlo2(float a, float b) {
    __nv_bfloat162 t;
    t.x = __float2bfloat16_rn(a - __bfloat162float(__float2bfloat16_rn(a)));
    t.y = __float2bfloat16_rn(b - __bfloat162float(__float2bfloat16_rn(b)));
    return *(unsigned*)&t;
}

// ---------------- LayerNorm -> bf16 hi/lo split output ----------------
__global__ void ln_split_kernel(const float* __restrict__ x,
                                const float* __restrict__ gamma,
                                const float* __restrict__ beta,
                                bf16* __restrict__ oh, bf16* __restrict__ ol) {
    int row = blockIdx.x;
    int t = threadIdx.x;
    const float4* xr = (const float4*)(x + (size_t)row * DMODEL);
    float4 v = xr[t];
    float s  = v.x + v.y + v.z + v.w;
    float ss = v.x * v.x + v.y * v.y + v.z * v.z + v.w * v.w;
    #pragma unroll
    for (int o = 16; o > 0; o >>= 1) {
        s  += __shfl_xor_sync(0xFFFFFFFFu, s,  o);
        ss += __shfl_xor_sync(0xFFFFFFFFu, ss, o);
    }
    __shared__ float rs[8], rss[8];
    int wid = t >> 5, lid = t & 31;
    if (lid == 0) { rs[wid] = s; rss[wid] = ss; }
    __syncthreads();
    s = 0.f; ss = 0.f;
    #pragma unroll
    for (int i = 0; i < 8; i++) { s += rs[i]; ss += rss[i]; }
    float mean = s * (1.0f / DMODEL);
    float var  = (ss - (float)DMODEL * mean * mean) * (1.0f / (DMODEL - 1));
    float inv  = 1.0f / (sqrtf(fmaxf(var, 0.0f)) + LN_EPS);
    const float4 gg = ((const float4*)gamma)[t];
    const float4 bb = ((const float4*)beta)[t];
    float o4[4];
    o4[0] = gg.x * (v.x - mean) * inv + bb.x;
    o4[1] = gg.y * (v.y - mean) * inv + bb.y;
    o4[2] = gg.z * (v.z - mean) * inv + bb.z;
    o4[3] = gg.w * (v.w - mean) * inv + bb.w;
    bf16 hh[4], ll[4];
    #pragma unroll
    for (int j = 0; j < 4; j++) split2(o4[j], hh[j], ll[j]);
    size_t base = (size_t)row * DMODEL + t * 4;
    *(uint2*)(oh + base) = *(uint2*)hh;
    *(uint2*)(ol + base) = *(uint2*)ll;
}

// ---------------- Weight transpose + split: [K,N] fp32 -> [N][K] bf16 hi/lo ----
__global__ void wsplit_tr_kernel(const float* __restrict__ W,
                                 bf16* __restrict__ Th, bf16* __restrict__ Tl,
                                 int K, int N) {
    __shared__ float t[32][33];
    int n0 = blockIdx.x * 32, k0 = blockIdx.y * 32;
    int tx = threadIdx.x, ty = threadIdx.y;   // 32 x 8
    #pragma unroll
    for (int i = 0; i < 4; i++)
        t[ty + 8 * i][tx] = W[(size_t)(k0 + ty + 8 * i) * N + n0 + tx];
    __syncthreads();
    #pragma unroll
    for (int i = 0; i < 4; i++) {
        float f = t[tx][ty + 8 * i];
        bf16 h, l; split2(f, h, l);
        size_t o = (size_t)(n0 + ty + 8 * i) * K + k0 + tx;
        Th[o] = h; Tl[o] = l;
    }
}

// ---------------- Fused QKV weight split: z selects w_q/w_k/w_v ----------------
__global__ void wsplit_qkv_kernel(const float* __restrict__ Wq,
                                  const float* __restrict__ Wk,
                                  const float* __restrict__ Wv,
                                  bf16* __restrict__ Th, bf16* __restrict__ Tl) {
    __shared__ float t[32][33];
    int z = blockIdx.z;
    const float* W = (z == 0) ? Wq : (z == 1) ? Wk : Wv;
    bf16* oh = Th + (size_t)z * 1024 * DMODEL;
    bf16* ol = Tl + (size_t)z * 1024 * DMODEL;
    int n0 = blockIdx.x * 32, k0 = blockIdx.y * 32;
    int tx = threadIdx.x, ty = threadIdx.y;   // 32 x 8
    #pragma unroll
    for (int i = 0; i < 4; i++)
        t[ty + 8 * i][tx] = W[(size_t)(k0 + ty + 8 * i) * DMODEL + n0 + tx];
    __syncthreads();
    #pragma unroll
    for (int i = 0; i < 4; i++) {
        float f = t[tx][ty + 8 * i];
        bf16 h, l; split2(f, h, l);
        size_t o = (size_t)(n0 + ty + 8 * i) * DMODEL + k0 + tx;
        oh[o] = h; ol[o] = l;
    }
}

// ---------------- V transpose: packed qkv [row][3072] col 2048+ -> [b,h,d,s] ----
__global__ void vtr_kernel(const bf16* __restrict__ V, bf16* __restrict__ Vt) {
    __shared__ bf16 t[32][33];
    int s0 = blockIdx.x * 32, d0 = blockIdx.y * 32, z = blockIdx.z;  // z = b*16+h
    int bq = z >> 4, hq = z & 15;
    int tx = threadIdx.x, ty = threadIdx.y;    // 32 x 8
    #pragma unroll
    for (int i = 0; i < 4; i++)
        t[ty + 8 * i][tx] = V[(size_t)(bq * SEQ + s0 + ty + 8 * i) * QKVW + 2048 + hq * 64 + d0 + tx];
    __syncthreads();
    #pragma unroll
    for (int i = 0; i < 4; i++)
        Vt[(size_t)(z * 64 + d0 + ty + 8 * i) * SEQ + s0 + tx] = t[tx][ty + 8 * i];
}

// ---------------- common helpers ----------------
__device__ __forceinline__ void cpa16(uint32_t d, const void* s) {
    asm volatile("cp.async.cg.shared.global [%0], [%1], 16;" :: "r"(d), "l"(s));
}
__device__ __forceinline__ void cpcommit() {
    asm volatile("cp.async.commit_group;");
}
template<int W> __device__ __forceinline__ void cpwait() {
    asm volatile("cp.async.wait_group %0;" :: "n"(W));
}
__device__ __forceinline__ void mma16816(float c[4], const unsigned a[4], const unsigned b[2]) {
    asm volatile(
        "mma.sync.aligned.m16n8k16.row.col.f32.bf16.bf16.f32 "
        "{%0,%1,%2,%3}, {%4,%5,%6,%7}, {%8,%9}, {%0,%1,%2,%3};\n"
        : "+f"(c[0]), "+f"(c[1]), "+f"(c[2]), "+f"(c[3])
        : "r"(a[0]), "r"(a[1]), "r"(a[2]), "r"(a[3]), "r"(b[0]), "r"(b[1]));
}

// ---------------- Tensor-core GEMM: EXACT R6/R11 structure ----------------------
// A(hi/lo): [M][K] bf16 rm. B(hi/lo): [N][K] bf16 (k-contiguous). C = act(A@B^T)+res.
#define BM 128
#define BN 128
#define BK 32
#define SKP 40
#define TILE_B (128 * SKP * 2)      // 10240 B
#define STAGE_B (4 * TILE_B)        // 40960 B

__device__ __forceinline__ void fill_stage(uint32_t sb,
        const bf16* __restrict__ Agh, const bf16* __restrict__ Agl,
        const bf16* __restrict__ Bgh, const bf16* __restrict__ Bgl,
        int row0, int col0, int k0, int K, int tid) {
    int r  = tid >> 1;
    int kb = (tid & 1) * 32;
    size_t aoff = ((size_t)(row0 + r) * K + k0) * 2 + kb;
    size_t boff = ((size_t)(col0 + r) * K + k0) * 2 + kb;
    uint32_t dst = sb + (uint32_t)r * (SKP * 2) + kb;
    cpa16(dst,                   (const char*)Agh + aoff);
    cpa16(dst + 16,              (const char*)Agh + aoff + 16);
    cpa16(dst + TILE_B,          (const char*)Agl + aoff);
    cpa16(dst + TILE_B + 16,     (const char*)Agl + aoff + 16);
    cpa16(dst + 2 * TILE_B,      (const char*)Bgh + boff);
    cpa16(dst + 2 * TILE_B + 16, (const char*)Bgh + boff + 16);
    cpa16(dst + 3 * TILE_B,      (const char*)Bgl + boff);
    cpa16(dst + 3 * TILE_B + 16, (const char*)Bgl + boff + 16);
}

template<bool RELU, bool SPLIT>
__global__ __launch_bounds__(256)
void gemm_mma(const bf16* __restrict__ Agh, const bf16* __restrict__ Agl,
              const bf16* __restrict__ Bgh, const bf16* __restrict__ Bgl,
              const float* __restrict__ bias, const float* __restrict__ res,
              float* __restrict__ C, bf16* __restrict__ Ch, bf16* __restrict__ Cl,
              int M, int N, int K) {
    extern __shared__ bf16 smem[];
    uint32_t sbase = (uint32_t)__cvta_generic_to_shared(smem);
    int tid = threadIdx.x, lane = tid & 31, warp = tid >> 5;
    int g = lane >> 2, tig = lane & 3;
    int m_base = (warp & 1) * 64, n_base = (warp >> 1) * 32;
    int row0 = blockIdx.y * BM, col0 = blockIdx.x * BN;

    float acc[4][4][4];
    #pragma unroll
    for (int mi = 0; mi < 4; mi++)
        #pragma unroll
        for (int ni = 0; ni < 4; ni++)
            #pragma unroll
            for (int r = 0; r < 4; r++) acc[mi][ni][r] = 0.0f;

    int NIT = K >> 5;
    fill_stage(sbase, Agh, Agl, Bgh, Bgl, row0, col0, 0, K, tid);
    cpcommit();

    for (int it = 0; it < NIT; ++it) {
        if (it + 1 < NIT) {
            fill_stage(sbase + ((it + 1) & 1) * STAGE_B, Agh, Agl, Bgh, Bgl,
                       row0, col0, (it + 1) << 5, K, tid);
            cpcommit();
            cpwait<1>();
        } else {
            cpwait<0>();
        }
        __syncthreads();

        const bf16* st  = smem + (it & 1) * (STAGE_B / 2);
        const bf16* Ahs = st;
        const bf16* Als = st + TILE_B / 2;
        const bf16* Bhs = st + 2 * (TILE_B / 2);
        const bf16* Bls = st + 3 * (TILE_B / 2);

        #pragma unroll
        for (int ks = 0; ks < 2; ks++) {
            int kk = ks * 16;
            unsigned a_h[4][4], a_l[4][4], b_h[4][2], b_l[4][2];
            #pragma unroll
            for (int mi = 0; mi < 4; mi++) {
                int r = m_base + mi * 16 + g;
                int base = r * SKP + kk + 2 * tig;
                a_h[mi][0] = *(const unsigned*)(Ahs + base);
                a_h[mi][1] = *(const unsigned*)(Ahs + base + 8 * SKP);
                a_h[mi][2] = *(const unsigned*)(Ahs + base + 8);
                a_h[mi][3] = *(const unsigned*)(Ahs + base + 8 * SKP + 8);
                a_l[mi][0] = *(const unsigned*)(Als + base);
                a_l[mi][1] = *(const unsigned*)(Als + base + 8 * SKP);
                a_l[mi][2] = *(const unsigned*)(Als + base + 8);
                a_l[mi][3] = *(const unsigned*)(Als + base + 8 * SKP + 8);
            }
            #pragma unroll
            for (int ni = 0; ni < 4; ni++) {
                int n = n_base + ni * 8 + g;
                int base = n * SKP + kk + 2 * tig;
                b_h[ni][0] = *(const unsigned*)(Bhs + base);
                b_h[ni][1] = *(const unsigned*)(Bhs + base + 8);
                b_l[ni][0] = *(const unsigned*)(Bls + base);
                b_l[ni][1] = *(const unsigned*)(Bls + base + 8);
            }
            #pragma unroll
            for (int mi = 0; mi < 4; mi++)
                #pragma unroll
                for (int ni = 0; ni < 4; ni++) {
                    mma16816(acc[mi][ni], a_h[mi], b_h[ni]);
                    mma16816(acc[mi][ni], a_h[mi], b_l[ni]);
                    mma16816(acc[mi][ni], a_l[mi], b_h[ni]);
                }
        }
        __syncthreads();
    }

    #pragma unroll
    for (int mi = 0; mi < 4; mi++) {
        #pragma unroll
        for (int ni = 0; ni < 4; ni++) {
            int r = row0 + m_base + mi * 16 + g;
            int c = col0 + n_base + ni * 8 + 2 * tig;
            float2 b2 = make_float2(0.f, 0.f);
            if (bias) b2 = *(const float2*)(bias + c);
            float2 v0, v1;
            v0.x = acc[mi][ni][0] + b2.x; v0.y = acc[mi][ni][1] + b2.y;
            v1.x = acc[mi][ni][2] + b2.x; v1.y = acc[mi][ni][3] + b2.y;
            if (RELU) {
                v0.x = fmaxf(v0.x, 0.f); v0.y = fmaxf(v0.y, 0.f);
                v1.x = fmaxf(v1.x, 0.f); v1.y = fmaxf(v1.y, 0.f);
            }
            if (res) {
                float2 r0 = *(const float2*)(res + (size_t)r * N + c);
                float2 r1 = *(const float2*)(res + (size_t)(r + 8) * N + c);
                v0.x += r0.x; v0.y += r0.y; v1.x += r1.x; v1.y += r1.y;
            }
            if (SPLIT) {
                *(unsigned*)(Ch + (size_t)r * N + c)       = packbf2(v0.x, v0.y);
                *(unsigned*)(Ch + (size_t)(r + 8) * N + c) = packbf2(v1.x, v1.y);
                *(unsigned*)(Cl + (size_t)r * N + c)       = packlo2(v0.x, v0.y);
                *(unsigned*)(Cl + (size_t)(r + 8) * N + c) = packlo2(v1.x, v1.y);
            } else {
                *(float2*)(C + (size_t)r * N + c)       = v0;
                *(float2*)(C + (size_t)(r + 8) * N + c) = v1;
            }
        }
    }
}

// ---------------- MMA flash attention (R11; packed QKV input) ----------
#define AQT 128
#define ASK 72
#define AROWB (ASK * 2)
#define ATILE (64 * AROWB)
#define ASTAGE (4 * ATILE)

__device__ __forceinline__ void attn_fill(uint32_t sb, int stage,
        const bf16* __restrict__ QKVh, const bf16* __restrict__ QKVl,
        const bf16* __restrict__ Vth, const bf16* __restrict__ Vtl,
        int b, int h, int kt, int tid) {
    int r  = tid >> 2;
    int q4 = (tid & 3) * 32;
    size_t koff = ((size_t)(b * SEQ + kt * 64 + r) * QKVW + 1024 + h * 64) * 2 + q4;
    size_t voff = ((size_t)((b * NHEAD + h) * 64 + r) * SEQ + kt * 64) * 2 + q4;
    uint32_t d = sb + stage * ASTAGE + (uint32_t)r * AROWB + q4;
    cpa16(d,                  (const char*)QKVh + koff);
    cpa16(d + 16,             (const char*)QKVh + koff + 16);
    cpa16(d + ATILE,          (const char*)QKVl + koff);
    cpa16(d + ATILE + 16,     (const char*)QKVl + koff + 16);
    cpa16(d + 2 * ATILE,      (const char*)Vth + voff);
    cpa16(d + 2 * ATILE + 16, (const char*)Vth + voff + 16);
    cpa16(d + 3 * ATILE,      (const char*)Vtl + voff);
    cpa16(d + 3 * ATILE + 16, (const char*)Vtl + voff + 16);
}

__global__ __launch_bounds__(256)
void attn_mma_kernel(const bf16* __restrict__ QKVh, const bf16* __restrict__ QKVl,
                     const bf16* __restrict__ Vth, const bf16* __restrict__ Vtl,
                     bf16* __restrict__ Oh, bf16* __restrict__ Ol) {
    extern __shared__ char smraw[];
    uint32_t sb = (uint32_t)__cvta_generic_to_shared(smraw);
    int b = blockIdx.z, h = blockIdx.y, qb = blockIdx.x * AQT;
    int tid = threadIdx.x, lane = tid & 31, warp = tid >> 5;
    int g = lane >> 2, tig = lane & 3;

    {   // stage Q tile (128 x 64) hi/lo from packed cols [0,1024)
        int r = tid >> 1;
        int half = (tid & 1) * 64;
        size_t qoff = ((size_t)(b * SEQ + qb + r) * QKVW + h * 64) * 2 + half;
        uint32_t d0 = sb + (uint32_t)r * AROWB + half;
        #pragma unroll
        for (int i = 0; i < 4; i++) cpa16(d0 + 16 * i, (const char*)QKVh + qoff + 16 * i);
        uint32_t d1 = sb + 2 * ATILE + (uint32_t)r * AROWB + half;
        #pragma unroll
        for (int i = 0; i < 4; i++) cpa16(d1 + 16 * i, (const char*)QKVl + qoff + 16 * i);
    }
    cpcommit(); cpwait<0>(); __syncthreads();

    unsigned qfh[4][4], qfl[4][4];
    {
        const bf16* Qs_h = (const bf16*)smraw;
        const bf16* Qs_l = (const bf16*)(smraw + 2 * ATILE);
        int mrow = warp * 16 + g;
        #pragma unroll
        for (int ks = 0; ks < 4; ks++) {
            int base = mrow * ASK + ks * 16 + 2 * tig;
            qfh[ks][0] = *(const unsigned*)(Qs_h + base);
            qfh[ks][1] = *(const unsigned*)(Qs_h + base + 8 * ASK);
            qfh[ks][2] = *(const unsigned*)(Qs_h + base + 8);
            qfh[ks][3] = *(const unsigned*)(Qs_h + base + 8 * ASK + 8);
            qfl[ks][0] = *(const unsigned*)(Qs_l + base);
            qfl[ks][1] = *(const unsigned*)(Qs_l + base + 8 * ASK);
            qfl[ks][2] = *(const unsigned*)(Qs_l + base + 8);
            qfl[ks][3] = *(const unsigned*)(Qs_l + base + 8 * ASK + 8);
        }
    }
    __syncthreads();

    float oacc[8][4];
    #pragma unroll
    for (int nf = 0; nf < 8; nf++)
        #pragma unroll
        for (int c = 0; c < 4; c++) oacc[nf][c] = 0.f;
    float mrow[2] = {-1e30f, -1e30f}, lrow[2] = {0.f, 0.f};

    const int NKT = SEQ / 64;
    attn_fill(sb, 0, QKVh, QKVl, Vth, Vtl, b, h, 0, tid);
    cpcommit();

    for (int kt = 0; kt < NKT; kt++) {
        if (kt + 1 < NKT) {
            attn_fill(sb, (kt + 1) & 1, QKVh, QKVl, Vth, Vtl, b, h, kt + 1, tid);
            cpcommit();
            cpwait<1>();
        } else {
            cpwait<0>();
        }
        __syncthreads();

        const bf16* st   = (const bf16*)(smraw + (kt & 1) * ASTAGE);
        const bf16* Ks_h = st;
        const bf16* Ks_l = st + ATILE / 2;
        const bf16* Vs_h = st + 2 * (ATILE / 2);
        const bf16* Vs_l = st + 3 * (ATILE / 2);

        float sacc[8][4];
        #pragma unroll
        for (int nf = 0; nf < 8; nf++)
            #pragma unroll
            for (int c = 0; c < 4; c++) sacc[nf][c] = 0.f;
        #pragma unroll
        for (int ks = 0; ks < 4; ks++) {
            #pragma unroll
            for (int nf = 0; nf < 8; nf++) {
                int n = nf * 8 + g;
                int base = n * ASK + ks * 16 + 2 * tig;
                unsigned bh2[2], bl2[2];
                bh2[0] = *(const unsigned*)(Ks_h + base);
                bh2[1] = *(const unsigned*)(Ks_h + base + 8);
                bl2[0] = *(const unsigned*)(Ks_l + base);
                bl2[1] = *(const unsigned*)(Ks_l + base + 8);
                mma16816(sacc[nf], qfh[ks], bh2);
                mma16816(sacc[nf], qfh[ks], bl2);
                mma16816(sacc[nf], qfl[ks], bh2);
            }
        }

        #pragma unroll
        for (int nf = 0; nf < 8; nf++)
            #pragma unroll
            for (int c = 0; c < 4; c++) sacc[nf][c] *= 0.125f;

        #pragma unroll
        for (int rr = 0; rr < 2; rr++) {
            float rm = -1e30f;
            #pragma unroll
            for (int nf = 0; nf < 8; nf++)
                rm = fmaxf(rm, fmaxf(sacc[nf][2 * rr], sacc[nf][2 * rr + 1]));
            rm = fmaxf(rm, __shfl_xor_sync(0xFFFFFFFFu, rm, 1));
            rm = fmaxf(rm, __shfl_xor_sync(0xFFFFFFFFu, rm, 2));
            float mn = fmaxf(mrow[rr], rm);
            float al = __expf(mrow[rr] - mn);
            mrow[rr] = mn;
            float rs = 0.f;
            #pragma unroll
            for (int nf = 0; nf < 8; nf++) {
                sacc[nf][2 * rr]     = __expf(sacc[nf][2 * rr]     - mn);
                sacc[nf][2 * rr + 1] = __expf(sacc[nf][2 * rr + 1] - mn);
                rs += sacc[nf][2 * rr] + sacc[nf][2 * rr + 1];
            }
            rs += __shfl_xor_sync(0xFFFFFFFFu, rs, 1);
            rs += __shfl_xor_sync(0xFFFFFFFFu, rs, 2);
            lrow[rr] = lrow[rr] * al + rs;
            #pragma unroll
            for (int nf = 0; nf < 8; nf++) {
                oacc[nf][2 * rr]     *= al;
                oacc[nf][2 * rr + 1] *= al;
            }
        }

        #pragma unroll
        for (int ks = 0; ks < 4; ks++) {
            unsigned ph2[4], pl2[4];
            ph2[0] = packbf2(sacc[2 * ks][0],     sacc[2 * ks][1]);
            ph2[1] = packbf2(sacc[2 * ks][2],     sacc[2 * ks][3]);
            ph2[2] = packbf2(sacc[2 * ks + 1][0], sacc[2 * ks + 1][1]);
            ph2[3] = packbf2(sacc[2 * ks + 1][2], sacc[2 * ks + 1][3]);
            pl2[0] = packlo2(sacc[2 * ks][0],     sacc[2 * ks][1]);
            pl2[1] = packlo2(sacc[2 * ks][2],     sacc[2 * ks][3]);
            pl2[2] = packlo2(sacc[2 * ks + 1][0], sacc[2 * ks + 1][1]);
            pl2[3] = packlo2(sacc[2 * ks + 1][2], sacc[2 * ks + 1][3]);
            #pragma unroll
            for (int nf = 0; nf < 8; nf++) {
                int n = nf * 8 + g;
                int base = n * ASK + ks * 16 + 2 * tig;
                unsigned vh2[2], vl2[2];
                vh2[0] = *(const unsigned*)(Vs_h + base);
                vh2[1] = *(const unsigned*)(Vs_h + base + 8);
                vl2[0] = *(const unsigned*)(Vs_l + base);
                vl2[1] = *(const unsigned*)(Vs_l + base + 8);
                mma16816(oacc[nf], ph2, vh2);
                mma16816(oacc[nf], ph2, vl2);
                mma16816(oacc[nf], pl2, vh2);
            }
        }
        __syncthreads();
    }

    #pragma unroll
    for (int rr = 0; rr < 2; rr++) {
        float inv = 1.0f / lrow[rr];
        size_t r_glob = (size_t)(b * SEQ + qb + warp * 16 + g + rr * 8);
        #pragma unroll
        for (int nf = 0; nf < 8; nf++) {
            int col = h * 64 + nf * 8 + 2 * tig;
            float o0 = oacc[nf][2 * rr] * inv;
            float o1 = oacc[nf][2 * rr + 1] * inv;
            *(unsigned*)(Oh + r_glob * DMODEL + col) = packbf2(o0, o1);
            *(unsigned*)(Ol + r_glob * DMODEL + col) = packlo2(o0, o1);
        }
    }
}

// ---------------- launch ----------------
extern "C" void kernel_launch(void* const* d_in, const int* in_sizes, int n_in,
                              void* d_out, int out_size) {
    const float* x   = (const float*)d_in[0];
    const float* w_q = (const float*)d_in[1];
    const float* w_k = (const float*)d_in[2];
    const float* w_v = (const float*)d_in[3];
    const float* w_o = (const float*)d_in[4];
    const float* w1  = (const float*)d_in[5];
    const float* b1  = (const float*)d_in[6];
    const float* w2  = (const float*)d_in[7];
    const float* b2  = (const float*)d_in[8];
    const float* g1  = (const float*)d_in[9];
    const float* be1 = (const float*)d_in[10];
    const float* g2  = (const float*)d_in[11];
    const float* be2 = (const float*)d_in[12];
    float* out = (float*)d_out;

    float *x1;
    bf16 *lnh, *lnl, *qkvh, *qkvl, *vth, *vtl, *atth, *attl, *ffh, *ffl;
    bf16 *wqkvh, *wqkvl, *woh, *wol, *w1h, *w1l, *w2h, *w2l;
    cudaGetSymbolAddress((void**)&x1,    g_x1);
    cudaGetSymbolAddress((void**)&lnh,   g_lnh);   cudaGetSymbolAddress((void**)&lnl,   g_lnl);
    cudaGetSymbolAddress((void**)&qkvh,  g_qkvh);  cudaGetSymbolAddress((void**)&qkvl,  g_qkvl);
    cudaGetSymbolAddress((void**)&vth,   g_vth);   cudaGetSymbolAddress((void**)&vtl,   g_vtl);
    cudaGetSymbolAddress((void**)&atth,  g_atth);  cudaGetSymbolAddress((void**)&attl,  g_attl);
    cudaGetSymbolAddress((void**)&ffh,   g_ffh);   cudaGetSymbolAddress((void**)&ffl,   g_ffl);
    cudaGetSymbolAddress((void**)&wqkvh, g_wqkvh); cudaGetSymbolAddress((void**)&wqkvl, g_wqkvl);
    cudaGetSymbolAddress((void**)&woh,   g_woh);   cudaGetSymbolAddress((void**)&wol,   g_wol);
    cudaGetSymbolAddress((void**)&w1h,   g_w1h);   cudaGetSymbolAddress((void**)&w1l,   g_w1l);
    cudaGetSymbolAddress((void**)&w2h,   g_w2h);   cudaGetSymbolAddress((void**)&w2l,   g_w2l);

    const int gemm_smem = 2 * STAGE_B;   // 81920 B
    cudaFuncSetAttribute(gemm_mma<false, false>, cudaFuncAttributeMaxDynamicSharedMemorySize, gemm_smem);
    cudaFuncSetAttribute(gemm_mma<false, true >, cudaFuncAttributeMaxDynamicSharedMemorySize, gemm_smem);
    cudaFuncSetAttribute(gemm_mma<true,  true >, cudaFuncAttributeMaxDynamicSharedMemorySize, gemm_smem);
    const int attn_smem = 2 * ASTAGE;
    cudaFuncSetAttribute(attn_mma_kernel, cudaFuncAttributeMaxDynamicSharedMemorySize, attn_smem);

    dim3 wb(32, 8);
    dim3 gQKV (QKVW / BN, ROWS / BM);    // 24 x 32 = 768 CTAs
    dim3 gProj(DMODEL / BN, ROWS / BM);  // 8 x 32
    dim3 gFF1 (FFDIM / BN, ROWS / BM);   // 32 x 32

    // launch 0: LN1
    ln_split_kernel<<<ROWS, 256>>>(x, g1, be1, lnh, lnl);
    // launch 1: fused QKV weight split (grid.z = 3)
    wsplit_qkv_kernel<<<dim3(DMODEL/32, DMODEL/32, 3), wb>>>(w_q, w_k, w_v, wqkvh, wqkvl);
    // launch 2: w_o split
    wsplit_tr_kernel<<<dim3(DMODEL/32, DMODEL/32), wb>>>(w_o, woh, wol, DMODEL, DMODEL);
    // launch 3: fused QKV GEMM  (<- effective profiled index)
    gemm_mma<false,true><<<gQKV, 256, gemm_smem>>>(lnh, lnl, wqkvh, wqkvl, nullptr, nullptr, nullptr, qkvh, qkvl, ROWS, QKVW, DMODEL);
    // remaining weight preps
    wsplit_tr_kernel<<<dim3(FFDIM/32,  DMODEL/32), wb>>>(w1, w1h, w1l, DMODEL, FFDIM);
    wsplit_tr_kernel<<<dim3(DMODEL/32, FFDIM/32),  wb>>>(w2, w2h, w2l, FFDIM, DMODEL);
    // V transpose to [b,h,d,s] (reads packed v block)
    vtr_kernel<<<dim3(SEQ/32, 2, 32), wb>>>(qkvh, vth);
    vtr_kernel<<<dim3(SEQ/32, 2, 32), wb>>>(qkvl, vtl);
    // MMA attention -> split output
    attn_mma_kernel<<<dim3(SEQ/AQT, NHEAD, 2), 256, attn_smem>>>(qkvh, qkvl, vth, vtl, atth, attl);
    // output projection + residual (fp32 out)
    gemm_mma<false,false><<<gProj, 256, gemm_smem>>>(atth, attl, woh, wol, nullptr, x, x1, nullptr, nullptr, ROWS, DMODEL, DMODEL);
    // LN2 -> split
    ln_split_kernel<<<ROWS, 256>>>(x1, g2, be2, lnh, lnl);
    // FFN
    gemm_mma<true, true ><<<gFF1,  256, gemm_smem>>>(lnh, lnl, w1h, w1l, b1, nullptr, nullptr, ffh, ffl, ROWS, FFDIM, DMODEL);
    gemm_mma<false,false><<<gProj, 256, gemm_smem>>>(ffh, ffl, w2h, w2l, b2, x1, out, nullptr, nullptr, ROWS, DMODEL, FFDIM);
}

// round 17
// speedup vs baseline: 1.2504x; 1.1858x over previous
#include <cuda_runtime.h>
#include <cuda_bf16.h>
#include <cuda_fp16.h>
#include <math.h>
#include <stdint.h>

#define DMODEL 1024
#define NHEAD  16
#define FFDIM  4096
#define ROWS   4096      // B*S
#define SEQ    2048
#define QKVW   3072      // packed qkv width
#define LN_EPS 1e-6f

typedef __nv_bfloat16 bf16;
typedef __half hf;

// ---------------- scratch (no allocation allowed) ----------------
__device__ float g_x1[ROWS * DMODEL];

__device__ bf16 g_lnh  [ROWS * DMODEL],   g_lnl  [ROWS * DMODEL];
__device__ bf16 g_qkvh [ROWS * QKVW],     g_qkvl [ROWS * QKVW];    // [row][q|k|v]
__device__ bf16 g_vth  [ROWS * DMODEL],   g_vtl  [ROWS * DMODEL];  // [b,h,d,s]
__device__ bf16 g_atth [ROWS * DMODEL],   g_attl [ROWS * DMODEL];
__device__ bf16 g_wqkvh[QKVW * DMODEL],   g_wqkvl[QKVW * DMODEL];  // [n][k]
__device__ bf16 g_woh  [DMODEL * DMODEL], g_wol  [DMODEL * DMODEL];
// fp16 FFN path
__device__ hf g_l2h [ROWS * DMODEL], g_l2l [ROWS * DMODEL];
__device__ hf g_ffh [ROWS * FFDIM],  g_ffl [ROWS * FFDIM];
__device__ hf g_w1f [DMODEL * FFDIM];   // [n][k]
__device__ hf g_w2f [FFDIM * DMODEL];   // [n][k]

__device__ __forceinline__ void split2(float f, bf16& h, bf16& l) {
    h = __float2bfloat16_rn(f);
    l = __float2bfloat16_rn(f - __bfloat162float(h));
}
__device__ __forceinline__ unsigned packbf2(float a, float b) {
    __nv_bfloat162 t;
    t.x = __float2bfloat16_rn(a);
    t.y = __float2bfloat16_rn(b);
    return *(unsigned*)&t;
}
__device__ __forceinline__ unsigned packlo2(float a, float b) {
    __nv_bfloat162 t;
    t.x = __float2bfloat16_rn(a - __bfloat162float(__float2bfloat16_rn(a)));
    t.y = __float2bfloat16_rn(b - __bfloat162float(__float2bfloat16_rn(b)));
    return *(unsigned*)&t;
}
__device__ __forceinline__ unsigned packh2(float a, float b) {
    __half2 t;
    t.x = __float2half_rn(a);
    t.y = __float2half_rn(b);
    return *(unsigned*)&t;
}
__device__ __forceinline__ unsigned packhr2(float a, float b) {
    __half2 t;
    t.x = __float2half_rn(a - __half2float(__float2half_rn(a)));
    t.y = __float2half_rn(b - __half2float(__float2half_rn(b)));
    return *(unsigned*)&t;
}

// ---------------- LayerNorm -> bf16 hi/lo split output (LN1) ----------------
__global__ void ln_split_kernel(const float* __restrict__ x,
                                const float* __restrict__ gamma,
                                const float* __restrict__ beta,
                                bf16* __restrict__ oh, bf16* __restrict__ ol) {
    int row = blockIdx.x;
    int t = threadIdx.x;
    const float4* xr = (const float4*)(x + (size_t)row * DMODEL);
    float4 v = xr[t];
    float s  = v.x + v.y + v.z + v.w;
    float ss = v.x * v.x + v.y * v.y + v.z * v.z + v.w * v.w;
    #pragma unroll
    for (int o = 16; o > 0; o >>= 1) {
        s  += __shfl_xor_sync(0xFFFFFFFFu, s,  o);
        ss += __shfl_xor_sync(0xFFFFFFFFu, ss, o);
    }
    __shared__ float rs[8], rss[8];
    int wid = t >> 5, lid = t & 31;
    if (lid == 0) { rs[wid] = s; rss[wid] = ss; }
    __syncthreads();
    s = 0.f; ss = 0.f;
    #pragma unroll
    for (int i = 0; i < 8; i++) { s += rs[i]; ss += rss[i]; }
    float mean = s * (1.0f / DMODEL);
    float var  = (ss - (float)DMODEL * mean * mean) * (1.0f / (DMODEL - 1));
    float inv  = 1.0f / (sqrtf(fmaxf(var, 0.0f)) + LN_EPS);
    const float4 gg = ((const float4*)gamma)[t];
    const float4 bb = ((const float4*)beta)[t];
    float o4[4];
    o4[0] = gg.x * (v.x - mean) * inv + bb.x;
    o4[1] = gg.y * (v.y - mean) * inv + bb.y;
    o4[2] = gg.z * (v.z - mean) * inv + bb.z;
    o4[3] = gg.w * (v.w - mean) * inv + bb.w;
    bf16 hh[4], ll[4];
    #pragma unroll
    for (int j = 0; j < 4; j++) split2(o4[j], hh[j], ll[j]);
    size_t base = (size_t)row * DMODEL + t * 4;
    *(uint2*)(oh + base) = *(uint2*)hh;
    *(uint2*)(ol + base) = *(uint2*)ll;
}

// ---------------- LayerNorm -> fp16 hi/lo split output (LN2) ----------------
__global__ void ln_split_h_kernel(const float* __restrict__ x,
                                  const float* __restrict__ gamma,
                                  const float* __restrict__ beta,
                                  hf* __restrict__ oh, hf* __restrict__ ol) {
    int row = blockIdx.x;
    int t = threadIdx.x;
    const float4* xr = (const float4*)(x + (size_t)row * DMODEL);
    float4 v = xr[t];
    float s  = v.x + v.y + v.z + v.w;
    float ss = v.x * v.x + v.y * v.y + v.z * v.z + v.w * v.w;
    #pragma unroll
    for (int o = 16; o > 0; o >>= 1) {
        s  += __shfl_xor_sync(0xFFFFFFFFu, s,  o);
        ss += __shfl_xor_sync(0xFFFFFFFFu, ss, o);
    }
    __shared__ float rs[8], rss[8];
    int wid = t >> 5, lid = t & 31;
    if (lid == 0) { rs[wid] = s; rss[wid] = ss; }
    __syncthreads();
    s = 0.f; ss = 0.f;
    #pragma unroll
    for (int i = 0; i < 8; i++) { s += rs[i]; ss += rss[i]; }
    float mean = s * (1.0f / DMODEL);
    float var  = (ss - (float)DMODEL * mean * mean) * (1.0f / (DMODEL - 1));
    float inv  = 1.0f / (sqrtf(fmaxf(var, 0.0f)) + LN_EPS);
    const float4 gg = ((const float4*)gamma)[t];
    const float4 bb = ((const float4*)beta)[t];
    float o4[4];
    o4[0] = gg.x * (v.x - mean) * inv + bb.x;
    o4[1] = gg.y * (v.y - mean) * inv + bb.y;
    o4[2] = gg.z * (v.z - mean) * inv + bb.z;
    o4[3] = gg.w * (v.w - mean) * inv + bb.w;
    unsigned h0 = packh2(o4[0], o4[1]), h1 = packh2(o4[2], o4[3]);
    unsigned l0 = packhr2(o4[0], o4[1]), l1 = packhr2(o4[2], o4[3]);
    size_t base = (size_t)row * DMODEL + t * 4;
    uint2 hp; hp.x = h0; hp.y = h1;
    uint2 lp; lp.x = l0; lp.y = l1;
    *(uint2*)(oh + base) = hp;
    *(uint2*)(ol + base) = lp;
}

// ---------------- Weight transpose + split: [K,N] fp32 -> [N][K] bf16 hi/lo ----
__global__ void wsplit_tr_kernel(const float* __restrict__ W,
                                 bf16* __restrict__ Th, bf16* __restrict__ Tl,
                                 int K, int N) {
    __shared__ float t[32][33];
    int n0 = blockIdx.x * 32, k0 = blockIdx.y * 32;
    int tx = threadIdx.x, ty = threadIdx.y;   // 32 x 8
    #pragma unroll
    for (int i = 0; i < 4; i++)
        t[ty + 8 * i][tx] = W[(size_t)(k0 + ty + 8 * i) * N + n0 + tx];
    __syncthreads();
    #pragma unroll
    for (int i = 0; i < 4; i++) {
        float f = t[tx][ty + 8 * i];
        bf16 h, l; split2(f, h, l);
        size_t o = (size_t)(n0 + ty + 8 * i) * K + k0 + tx;
        Th[o] = h; Tl[o] = l;
    }
}

// ---------------- Weight transpose: [K,N] fp32 -> [N][K] fp16 -------------------
__global__ void wtr_h_kernel(const float* __restrict__ W,
                             hf* __restrict__ Th, int K, int N) {
    __shared__ float t[32][33];
    int n0 = blockIdx.x * 32, k0 = blockIdx.y * 32;
    int tx = threadIdx.x, ty = threadIdx.y;
    #pragma unroll
    for (int i = 0; i < 4; i++)
        t[ty + 8 * i][tx] = W[(size_t)(k0 + ty + 8 * i) * N + n0 + tx];
    __syncthreads();
    #pragma unroll
    for (int i = 0; i < 4; i++) {
        size_t o = (size_t)(n0 + ty + 8 * i) * K + k0 + tx;
        Th[o] = __float2half_rn(t[tx][ty + 8 * i]);
    }
}

// ---------------- Fused QKV weight split: z selects w_q/w_k/w_v ----------------
__global__ void wsplit_qkv_kernel(const float* __restrict__ Wq,
                                  const float* __restrict__ Wk,
                                  const float* __restrict__ Wv,
                                  bf16* __restrict__ Th, bf16* __restrict__ Tl) {
    __shared__ float t[32][33];
    int z = blockIdx.z;
    const float* W = (z == 0) ? Wq : (z == 1) ? Wk : Wv;
    bf16* oh = Th + (size_t)z * 1024 * DMODEL;
    bf16* ol = Tl + (size_t)z * 1024 * DMODEL;
    int n0 = blockIdx.x * 32, k0 = blockIdx.y * 32;
    int tx = threadIdx.x, ty = threadIdx.y;
    #pragma unroll
    for (int i = 0; i < 4; i++)
        t[ty + 8 * i][tx] = W[(size_t)(k0 + ty + 8 * i) * DMODEL + n0 + tx];
    __syncthreads();
    #pragma unroll
    for (int i = 0; i < 4; i++) {
        float f = t[tx][ty + 8 * i];
        bf16 h, l; split2(f, h, l);
        size_t o = (size_t)(n0 + ty + 8 * i) * DMODEL + k0 + tx;
        oh[o] = h; ol[o] = l;
    }
}

// ---------------- V transpose: packed qkv [row][3072] col 2048+ -> [b,h,d,s] ----
__global__ void vtr_kernel(const bf16* __restrict__ V, bf16* __restrict__ Vt) {
    __shared__ bf16 t[32][33];
    int s0 = blockIdx.x * 32, d0 = blockIdx.y * 32, z = blockIdx.z;  // z = b*16+h
    int bq = z >> 4, hq = z & 15;
    int tx = threadIdx.x, ty = threadIdx.y;
    #pragma unroll
    for (int i = 0; i < 4; i++)
        t[ty + 8 * i][tx] = V[(size_t)(bq * SEQ + s0 + ty + 8 * i) * QKVW + 2048 + hq * 64 + d0 + tx];
    __syncthreads();
    #pragma unroll
    for (int i = 0; i < 4; i++)
        Vt[(size_t)(z * 64 + d0 + ty + 8 * i) * SEQ + s0 + tx] = t[tx][ty + 8 * i];
}

// ---------------- common helpers ----------------
__device__ __forceinline__ void cpa16(uint32_t d, const void* s) {
    asm volatile("cp.async.cg.shared.global [%0], [%1], 16;" :: "r"(d), "l"(s));
}
__device__ __forceinline__ void cpcommit() {
    asm volatile("cp.async.commit_group;");
}
template<int W> __device__ __forceinline__ void cpwait() {
    asm volatile("cp.async.wait_group %0;" :: "n"(W));
}
__device__ __forceinline__ void mma16816(float c[4], const unsigned a[4], const unsigned b[2]) {
    asm volatile(
        "mma.sync.aligned.m16n8k16.row.col.f32.bf16.bf16.f32 "
        "{%0,%1,%2,%3}, {%4,%5,%6,%7}, {%8,%9}, {%0,%1,%2,%3};\n"
        : "+f"(c[0]), "+f"(c[1]), "+f"(c[2]), "+f"(c[3])
        : "r"(a[0]), "r"(a[1]), "r"(a[2]), "r"(a[3]), "r"(b[0]), "r"(b[1]));
}
__device__ __forceinline__ void mmah(float c[4], const unsigned a[4], const unsigned b[2]) {
    asm volatile(
        "mma.sync.aligned.m16n8k16.row.col.f32.f16.f16.f32 "
        "{%0,%1,%2,%3}, {%4,%5,%6,%7}, {%8,%9}, {%0,%1,%2,%3};\n"
        : "+f"(c[0]), "+f"(c[1]), "+f"(c[2]), "+f"(c[3])
        : "r"(a[0]), "r"(a[1]), "r"(a[2]), "r"(a[3]), "r"(b[0]), "r"(b[1]));
}

// ---------------- bf16 3-product GEMM: EXACT R15 structure ----------------------
#define BM 128
#define BN 128
#define BK 32
#define SKP 40
#define TILE_B (128 * SKP * 2)      // 10240 B
#define STAGE_B (4 * TILE_B)        // 40960 B

__device__ __forceinline__ void fill_stage(uint32_t sb,
        const bf16* __restrict__ Agh, const bf16* __restrict__ Agl,
        const bf16* __restrict__ Bgh, const bf16* __restrict__ Bgl,
        int row0, int col0, int k0, int K, int tid) {
    int r  = tid >> 1;
    int kb = (tid & 1) * 32;
    size_t aoff = ((size_t)(row0 + r) * K + k0) * 2 + kb;
    size_t boff = ((size_t)(col0 + r) * K + k0) * 2 + kb;
    uint32_t dst = sb + (uint32_t)r * (SKP * 2) + kb;
    cpa16(dst,                   (const char*)Agh + aoff);
    cpa16(dst + 16,              (const char*)Agh + aoff + 16);
    cpa16(dst + TILE_B,          (const char*)Agl + aoff);
    cpa16(dst + TILE_B + 16,     (const char*)Agl + aoff + 16);
    cpa16(dst + 2 * TILE_B,      (const char*)Bgh + boff);
    cpa16(dst + 2 * TILE_B + 16, (const char*)Bgh + boff + 16);
    cpa16(dst + 3 * TILE_B,      (const char*)Bgl + boff);
    cpa16(dst + 3 * TILE_B + 16, (const char*)Bgl + boff + 16);
}

template<bool SPLIT>
__global__ __launch_bounds__(256)
void gemm_mma(const bf16* __restrict__ Agh, const bf16* __restrict__ Agl,
              const bf16* __restrict__ Bgh, const bf16* __restrict__ Bgl,
              const float* __restrict__ res,
              float* __restrict__ C, bf16* __restrict__ Ch, bf16* __restrict__ Cl,
              int M, int N, int K) {
    extern __shared__ bf16 smem[];
    uint32_t sbase = (uint32_t)__cvta_generic_to_shared(smem);
    int tid = threadIdx.x, lane = tid & 31, warp = tid >> 5;
    int g = lane >> 2, tig = lane & 3;
    int m_base = (warp & 1) * 64, n_base = (warp >> 1) * 32;
    int row0 = blockIdx.y * BM, col0 = blockIdx.x * BN;

    float acc[4][4][4];
    #pragma unroll
    for (int mi = 0; mi < 4; mi++)
        #pragma unroll
        for (int ni = 0; ni < 4; ni++)
            #pragma unroll
            for (int r = 0; r < 4; r++) acc[mi][ni][r] = 0.0f;

    int NIT = K >> 5;
    fill_stage(sbase, Agh, Agl, Bgh, Bgl, row0, col0, 0, K, tid);
    cpcommit();

    for (int it = 0; it < NIT; ++it) {
        if (it + 1 < NIT) {
            fill_stage(sbase + ((it + 1) & 1) * STAGE_B, Agh, Agl, Bgh, Bgl,
                       row0, col0, (it + 1) << 5, K, tid);
            cpcommit();
            cpwait<1>();
        } else {
            cpwait<0>();
        }
        __syncthreads();

        const bf16* st  = smem + (it & 1) * (STAGE_B / 2);
        const bf16* Ahs = st;
        const bf16* Als = st + TILE_B / 2;
        const bf16* Bhs = st + 2 * (TILE_B / 2);
        const bf16* Bls = st + 3 * (TILE_B / 2);

        #pragma unroll
        for (int ks = 0; ks < 2; ks++) {
            int kk = ks * 16;
            unsigned a_h[4][4], a_l[4][4], b_h[4][2], b_l[4][2];
            #pragma unroll
            for (int mi = 0; mi < 4; mi++) {
                int r = m_base + mi * 16 + g;
                int base = r * SKP + kk + 2 * tig;
                a_h[mi][0] = *(const unsigned*)(Ahs + base);
                a_h[mi][1] = *(const unsigned*)(Ahs + base + 8 * SKP);
                a_h[mi][2] = *(const unsigned*)(Ahs + base + 8);
                a_h[mi][3] = *(const unsigned*)(Ahs + base + 8 * SKP + 8);
                a_l[mi][0] = *(const unsigned*)(Als + base);
                a_l[mi][1] = *(const unsigned*)(Als + base + 8 * SKP);
                a_l[mi][2] = *(const unsigned*)(Als + base + 8);
                a_l[mi][3] = *(const unsigned*)(Als + base + 8 * SKP + 8);
            }
            #pragma unroll
            for (int ni = 0; ni < 4; ni++) {
                int n = n_base + ni * 8 + g;
                int base = n * SKP + kk + 2 * tig;
                b_h[ni][0] = *(const unsigned*)(Bhs + base);
                b_h[ni][1] = *(const unsigned*)(Bhs + base + 8);
                b_l[ni][0] = *(const unsigned*)(Bls + base);
                b_l[ni][1] = *(const unsigned*)(Bls + base + 8);
            }
            #pragma unroll
            for (int mi = 0; mi < 4; mi++)
                #pragma unroll
                for (int ni = 0; ni < 4; ni++) {
                    mma16816(acc[mi][ni], a_h[mi], b_h[ni]);
                    mma16816(acc[mi][ni], a_h[mi], b_l[ni]);
                    mma16816(acc[mi][ni], a_l[mi], b_h[ni]);
                }
        }
        __syncthreads();
    }

    #pragma unroll
    for (int mi = 0; mi < 4; mi++) {
        #pragma unroll
        for (int ni = 0; ni < 4; ni++) {
            int r = row0 + m_base + mi * 16 + g;
            int c = col0 + n_base + ni * 8 + 2 * tig;
            float2 v0, v1;
            v0.x = acc[mi][ni][0]; v0.y = acc[mi][ni][1];
            v1.x = acc[mi][ni][2]; v1.y = acc[mi][ni][3];
            if (res) {
                float2 r0 = *(const float2*)(res + (size_t)r * N + c);
                float2 r1 = *(const float2*)(res + (size_t)(r + 8) * N + c);
                v0.x += r0.x; v0.y += r0.y; v1.x += r1.x; v1.y += r1.y;
            }
            if (SPLIT) {
                *(unsigned*)(Ch + (size_t)r * N + c)       = packbf2(v0.x, v0.y);
                *(unsigned*)(Ch + (size_t)(r + 8) * N + c) = packbf2(v1.x, v1.y);
                *(unsigned*)(Cl + (size_t)r * N + c)       = packlo2(v0.x, v0.y);
                *(unsigned*)(Cl + (size_t)(r + 8) * N + c) = packlo2(v1.x, v1.y);
            } else {
                *(float2*)(C + (size_t)r * N + c)       = v0;
                *(float2*)(C + (size_t)(r + 8) * N + c) = v1;
            }
        }
    }
}

// ---------------- fp16 2-product GEMM (FFN only) --------------------------------
#define HSTAGE_B (3 * TILE_B)       // Ah, Al, B = 30720 B

__device__ __forceinline__ void fill_stage_h(uint32_t sb,
        const hf* __restrict__ Agh, const hf* __restrict__ Agl,
        const hf* __restrict__ Bg,
        int row0, int col0, int k0, int K, int tid) {
    int r  = tid >> 1;
    int kb = (tid & 1) * 32;
    size_t aoff = ((size_t)(row0 + r) * K + k0) * 2 + kb;
    size_t boff = ((size_t)(col0 + r) * K + k0) * 2 + kb;
    uint32_t dst = sb + (uint32_t)r * (SKP * 2) + kb;
    cpa16(dst,                   (const char*)Agh + aoff);
    cpa16(dst + 16,              (const char*)Agh + aoff + 16);
    cpa16(dst + TILE_B,          (const char*)Agl + aoff);
    cpa16(dst + TILE_B + 16,     (const char*)Agl + aoff + 16);
    cpa16(dst + 2 * TILE_B,      (const char*)Bg + boff);
    cpa16(dst + 2 * TILE_B + 16, (const char*)Bg + boff + 16);
}

template<bool RELU, bool SPLIT>
__global__ __launch_bounds__(256)
void gemm_h2(const hf* __restrict__ Agh, const hf* __restrict__ Agl,
             const hf* __restrict__ Bg,
             const float* __restrict__ bias, const float* __restrict__ res,
             float* __restrict__ C, hf* __restrict__ Ch, hf* __restrict__ Cl,
             int M, int N, int K) {
    extern __shared__ hf smemh[];
    uint32_t sbase = (uint32_t)__cvta_generic_to_shared(smemh);
    int tid = threadIdx.x, lane = tid & 31, warp = tid >> 5;
    int g = lane >> 2, tig = lane & 3;
    int m_base = (warp & 1) * 64, n_base = (warp >> 1) * 32;
    int row0 = blockIdx.y * BM, col0 = blockIdx.x * BN;

    float acc[4][4][4];
    #pragma unroll
    for (int mi = 0; mi < 4; mi++)
        #pragma unroll
        for (int ni = 0; ni < 4; ni++)
            #pragma unroll
            for (int r = 0; r < 4; r++) acc[mi][ni][r] = 0.0f;

    int NIT = K >> 5;
    fill_stage_h(sbase, Agh, Agl, Bg, row0, col0, 0, K, tid);
    cpcommit();

    for (int it = 0; it < NIT; ++it) {
        if (it + 1 < NIT) {
            fill_stage_h(sbase + ((it + 1) & 1) * HSTAGE_B, Agh, Agl, Bg,
                         row0, col0, (it + 1) << 5, K, tid);
            cpcommit();
            cpwait<1>();
        } else {
            cpwait<0>();
        }
        __syncthreads();

        const hf* st  = smemh + (it & 1) * (HSTAGE_B / 2);
        const hf* Ahs = st;
        const hf* Als = st + TILE_B / 2;
        const hf* Bhs = st + 2 * (TILE_B / 2);

        #pragma unroll
        for (int ks = 0; ks < 2; ks++) {
            int kk = ks * 16;
            unsigned a_h[4][4], a_l[4][4], b_h[4][2];
            #pragma unroll
            for (int mi = 0; mi < 4; mi++) {
                int r = m_base + mi * 16 + g;
                int base = r * SKP + kk + 2 * tig;
                a_h[mi][0] = *(const unsigned*)(Ahs + base);
                a_h[mi][1] = *(const unsigned*)(Ahs + base + 8 * SKP);
                a_h[mi][2] = *(const unsigned*)(Ahs + base + 8);
                a_h[mi][3] = *(const unsigned*)(Ahs + base + 8 * SKP + 8);
                a_l[mi][0] = *(const unsigned*)(Als + base);
                a_l[mi][1] = *(const unsigned*)(Als + base + 8 * SKP);
                a_l[mi][2] = *(const unsigned*)(Als + base + 8);
                a_l[mi][3] = *(const unsigned*)(Als + base + 8 * SKP + 8);
            }
            #pragma unroll
            for (int ni = 0; ni < 4; ni++) {
                int n = n_base + ni * 8 + g;
                int base = n * SKP + kk + 2 * tig;
                b_h[ni][0] = *(const unsigned*)(Bhs + base);
                b_h[ni][1] = *(const unsigned*)(Bhs + base + 8);
            }
            #pragma unroll
            for (int mi = 0; mi < 4; mi++)
                #pragma unroll
                for (int ni = 0; ni < 4; ni++) {
                    mmah(acc[mi][ni], a_h[mi], b_h[ni]);
                    mmah(acc[mi][ni], a_l[mi], b_h[ni]);
                }
        }
        __syncthreads();
    }

    #pragma unroll
    for (int mi = 0; mi < 4; mi++) {
        #pragma unroll
        for (int ni = 0; ni < 4; ni++) {
            int r = row0 + m_base + mi * 16 + g;
            int c = col0 + n_base + ni * 8 + 2 * tig;
            float2 b2 = make_float2(0.f, 0.f);
            if (bias) b2 = *(const float2*)(bias + c);
            float2 v0, v1;
            v0.x = acc[mi][ni][0] + b2.x; v0.y = acc[mi][ni][1] + b2.y;
            v1.x = acc[mi][ni][2] + b2.x; v1.y = acc[mi][ni][3] + b2.y;
            if (RELU) {
                v0.x = fmaxf(v0.x, 0.f); v0.y = fmaxf(v0.y, 0.f);
                v1.x = fmaxf(v1.x, 0.f); v1.y = fmaxf(v1.y, 0.f);
            }
            if (res) {
                float2 r0 = *(const float2*)(res + (size_t)r * N + c);
                float2 r1 = *(const float2*)(res + (size_t)(r + 8) * N + c);
                v0.x += r0.x; v0.y += r0.y; v1.x += r1.x; v1.y += r1.y;
            }
            if (SPLIT) {
                *(unsigned*)(Ch + (size_t)r * N + c)       = packh2(v0.x, v0.y);
                *(unsigned*)(Ch + (size_t)(r + 8) * N + c) = packh2(v1.x, v1.y);
                *(unsigned*)(Cl + (size_t)r * N + c)       = packhr2(v0.x, v0.y);
                *(unsigned*)(Cl + (size_t)(r + 8) * N + c) = packhr2(v1.x, v1.y);
            } else {
                *(float2*)(C + (size_t)r * N + c)       = v0;
                *(float2*)(C + (size_t)(r + 8) * N + c) = v1;
            }
        }
    }
}

// ---------------- MMA flash attention (R15; bf16, packed QKV input) ----------
#define AQT 128
#define ASK 72
#define AROWB (ASK * 2)
#define ATILE (64 * AROWB)
#define ASTAGE (4 * ATILE)

__device__ __forceinline__ void attn_fill(uint32_t sb, int stage,
        const bf16* __restrict__ QKVh, const bf16* __restrict__ QKVl,
        const bf16* __restrict__ Vth, const bf16* __restrict__ Vtl,
        int b, int h, int kt, int tid) {
    int r  = tid >> 2;
    int q4 = (tid & 3) * 32;
    size_t koff = ((size_t)(b * SEQ + kt * 64 + r) * QKVW + 1024 + h * 64) * 2 + q4;
    size_t voff = ((size_t)((b * NHEAD + h) * 64 + r) * SEQ + kt * 64) * 2 + q4;
    uint32_t d = sb + stage * ASTAGE + (uint32_t)r * AROWB + q4;
    cpa16(d,                  (const char*)QKVh + koff);
    cpa16(d + 16,             (const char*)QKVh + koff + 16);
    cpa16(d + ATILE,          (const char*)QKVl + koff);
    cpa16(d + ATILE + 16,     (const char*)QKVl + koff + 16);
    cpa16(d + 2 * ATILE,      (const char*)Vth + voff);
    cpa16(d + 2 * ATILE + 16, (const char*)Vth + voff + 16);
    cpa16(d + 3 * ATILE,      (const char*)Vtl + voff);
    cpa16(d + 3 * ATILE + 16, (const char*)Vtl + voff + 16);
}

__global__ __launch_bounds__(256)
void attn_mma_kernel(const bf16* __restrict__ QKVh, const bf16* __restrict__ QKVl,
                     const bf16* __restrict__ Vth, const bf16* __restrict__ Vtl,
                     bf16* __restrict__ Oh, bf16* __restrict__ Ol) {
    extern __shared__ char smraw[];
    uint32_t sb = (uint32_t)__cvta_generic_to_shared(smraw);
    int b = blockIdx.z, h = blockIdx.y, qb = blockIdx.x * AQT;
    int tid = threadIdx.x, lane = tid & 31, warp = tid >> 5;
    int g = lane >> 2, tig = lane & 3;

    {
        int r = tid >> 1;
        int half = (tid & 1) * 64;
        size_t qoff = ((size_t)(b * SEQ + qb + r) * QKVW + h * 64) * 2 + half;
        uint32_t d0 = sb + (uint32_t)r * AROWB + half;
        #pragma unroll
        for (int i = 0; i < 4; i++) cpa16(d0 + 16 * i, (const char*)QKVh + qoff + 16 * i);
        uint32_t d1 = sb + 2 * ATILE + (uint32_t)r * AROWB + half;
        #pragma unroll
        for (int i = 0; i < 4; i++) cpa16(d1 + 16 * i, (const char*)QKVl + qoff + 16 * i);
    }
    cpcommit(); cpwait<0>(); __syncthreads();

    unsigned qfh[4][4], qfl[4][4];
    {
        const bf16* Qs_h = (const bf16*)smraw;
        const bf16* Qs_l = (const bf16*)(smraw + 2 * ATILE);
        int mrow = warp * 16 + g;
        #pragma unroll
        for (int ks = 0; ks < 4; ks++) {
            int base = mrow * ASK + ks * 16 + 2 * tig;
            qfh[ks][0] = *(const unsigned*)(Qs_h + base);
            qfh[ks][1] = *(const unsigned*)(Qs_h + base + 8 * ASK);
            qfh[ks][2] = *(const unsigned*)(Qs_h + base + 8);
            qfh[ks][3] = *(const unsigned*)(Qs_h + base + 8 * ASK + 8);
            qfl[ks][0] = *(const unsigned*)(Qs_l + base);
            qfl[ks][1] = *(const unsigned*)(Qs_l + base + 8 * ASK);
            qfl[ks][2] = *(const unsigned*)(Qs_l + base + 8);
            qfl[ks][3] = *(const unsigned*)(Qs_l + base + 8 * ASK + 8);
        }
    }
    __syncthreads();

    float oacc[8][4];
    #pragma unroll
    for (int nf = 0; nf < 8; nf++)
        #pragma unroll
        for (int c = 0; c < 4; c++) oacc[nf][c] = 0.f;
    float mrow[2] = {-1e30f, -1e30f}, lrow[2] = {0.f, 0.f};

    const int NKT = SEQ / 64;
    attn_fill(sb, 0, QKVh, QKVl, Vth, Vtl, b, h, 0, tid);
    cpcommit();

    for (int kt = 0; kt < NKT; kt++) {
        if (kt + 1 < NKT) {
            attn_fill(sb, (kt + 1) & 1, QKVh, QKVl, Vth, Vtl, b, h, kt + 1, tid);
            cpcommit();
            cpwait<1>();
        } else {
            cpwait<0>();
        }
        __syncthreads();

        const bf16* st   = (const bf16*)(smraw + (kt & 1) * ASTAGE);
        const bf16* Ks_h = st;
        const bf16* Ks_l = st + ATILE / 2;
        const bf16* Vs_h = st + 2 * (ATILE / 2);
        const bf16* Vs_l = st + 3 * (ATILE / 2);

        float sacc[8][4];
        #pragma unroll
        for (int nf = 0; nf < 8; nf++)
            #pragma unroll
            for (int c = 0; c < 4; c++) sacc[nf][c] = 0.f;
        #pragma unroll
        for (int ks = 0; ks < 4; ks++) {
            #pragma unroll
            for (int nf = 0; nf < 8; nf++) {
                int n = nf * 8 + g;
                int base = n * ASK + ks * 16 + 2 * tig;
                unsigned bh2[2], bl2[2];
                bh2[0] = *(const unsigned*)(Ks_h + base);
                bh2[1] = *(const unsigned*)(Ks_h + base + 8);
                bl2[0] = *(const unsigned*)(Ks_l + base);
                bl2[1] = *(const unsigned*)(Ks_l + base + 8);
                mma16816(sacc[nf], qfh[ks], bh2);
                mma16816(sacc[nf], qfh[ks], bl2);
                mma16816(sacc[nf], qfl[ks], bh2);
            }
        }

        #pragma unroll
        for (int nf = 0; nf < 8; nf++)
            #pragma unroll
            for (int c = 0; c < 4; c++) sacc[nf][c] *= 0.125f;

        #pragma unroll
        for (int rr = 0; rr < 2; rr++) {
            float rm = -1e30f;
            #pragma unroll
            for (int nf = 0; nf < 8; nf++)
                rm = fmaxf(rm, fmaxf(sacc[nf][2 * rr], sacc[nf][2 * rr + 1]));
            rm = fmaxf(rm, __shfl_xor_sync(0xFFFFFFFFu, rm, 1));
            rm = fmaxf(rm, __shfl_xor_sync(0xFFFFFFFFu, rm, 2));
            float mn = fmaxf(mrow[rr], rm);
            float al = __expf(mrow[rr] - mn);
            mrow[rr] = mn;
            float rs = 0.f;
            #pragma unroll
            for (int nf = 0; nf < 8; nf++) {
                sacc[nf][2 * rr]     = __expf(sacc[nf][2 * rr]     - mn);
                sacc[nf][2 * rr + 1] = __expf(sacc[nf][2 * rr + 1] - mn);
                rs += sacc[nf][2 * rr] + sacc[nf][2 * rr + 1];
            }
            rs += __shfl_xor_sync(0xFFFFFFFFu, rs, 1);
            rs += __shfl_xor_sync(0xFFFFFFFFu, rs, 2);
            lrow[rr] = lrow[rr] * al + rs;
            #pragma unroll
            for (int nf = 0; nf < 8; nf++) {
                oacc[nf][2 * rr]     *= al;
                oacc[nf][2 * rr + 1] *= al;
            }
        }

        #pragma unroll
        for (int ks = 0; ks < 4; ks++) {
            unsigned ph2[4], pl2[4];
            ph2[0] = packbf2(sacc[2 * ks][0],     sacc[2 * ks][1]);
            ph2[1] = packbf2(sacc[2 * ks][2],     sacc[2 * ks][3]);
            ph2[2] = packbf2(sacc[2 * ks + 1][0], sacc[2 * ks + 1][1]);
            ph2[3] = packbf2(sacc[2 * ks + 1][2], sacc[2 * ks + 1][3]);
            pl2[0] = packlo2(sacc[2 * ks][0],     sacc[2 * ks][1]);
            pl2[1] = packlo2(sacc[2 * ks][2],     sacc[2 * ks][3]);
            pl2[2] = packlo2(sacc[2 * ks + 1][0], sacc[2 * ks + 1][1]);
            pl2[3] = packlo2(sacc[2 * ks + 1][2], sacc[2 * ks + 1][3]);
            #pragma unroll
            for (int nf = 0; nf < 8; nf++) {
                int n = nf * 8 + g;
                int base = n * ASK + ks * 16 + 2 * tig;
                unsigned vh2[2], vl2[2];
                vh2[0] = *(const unsigned*)(Vs_h + base);
                vh2[1] = *(const unsigned*)(Vs_h + base + 8);
                vl2[0] = *(const unsigned*)(Vs_l + base);
                vl2[1] = *(const unsigned*)(Vs_l + base + 8);
                mma16816(oacc[nf], ph2, vh2);
                mma16816(oacc[nf], ph2, vl2);
                mma16816(oacc[nf], pl2, vh2);
            }
        }
        __syncthreads();
    }

    #pragma unroll
    for (int rr = 0; rr < 2; rr++) {
        float inv = 1.0f / lrow[rr];
        size_t r_glob = (size_t)(b * SEQ + qb + warp * 16 + g + rr * 8);
        #pragma unroll
        for (int nf = 0; nf < 8; nf++) {
            int col = h * 64 + nf * 8 + 2 * tig;
            float o0 = oacc[nf][2 * rr] * inv;
            float o1 = oacc[nf][2 * rr + 1] * inv;
            *(unsigned*)(Oh + r_glob * DMODEL + col) = packbf2(o0, o1);
            *(unsigned*)(Ol + r_glob * DMODEL + col) = packlo2(o0, o1);
        }
    }
}

// ---------------- launch ----------------
extern "C" void kernel_launch(void* const* d_in, const int* in_sizes, int n_in,
                              void* d_out, int out_size) {
    const float* x   = (const float*)d_in[0];
    const float* w_q = (const float*)d_in[1];
    const float* w_k = (const float*)d_in[2];
    const float* w_v = (const float*)d_in[3];
    const float* w_o = (const float*)d_in[4];
    const float* w1  = (const float*)d_in[5];
    const float* b1  = (const float*)d_in[6];
    const float* w2  = (const float*)d_in[7];
    const float* b2  = (const float*)d_in[8];
    const float* g1  = (const float*)d_in[9];
    const float* be1 = (const float*)d_in[10];
    const float* g2  = (const float*)d_in[11];
    const float* be2 = (const float*)d_in[12];
    float* out = (float*)d_out;

    float *x1;
    bf16 *lnh, *lnl, *qkvh, *qkvl, *vth, *vtl, *atth, *attl;
    bf16 *wqkvh, *wqkvl, *woh, *wol;
    hf *l2h, *l2l, *ffh, *ffl, *w1f, *w2f;
    cudaGetSymbolAddress((void**)&x1,    g_x1);
    cudaGetSymbolAddress((void**)&lnh,   g_lnh);   cudaGetSymbolAddress((void**)&lnl,   g_lnl);
    cudaGetSymbolAddress((void**)&qkvh,  g_qkvh);  cudaGetSymbolAddress((void**)&qkvl,  g_qkvl);
    cudaGetSymbolAddress((void**)&vth,   g_vth);   cudaGetSymbolAddress((void**)&vtl,   g_vtl);
    cudaGetSymbolAddress((void**)&atth,  g_atth);  cudaGetSymbolAddress((void**)&attl,  g_attl);
    cudaGetSymbolAddress((void**)&wqkvh, g_wqkvh); cudaGetSymbolAddress((void**)&wqkvl, g_wqkvl);
    cudaGetSymbolAddress((void**)&woh,   g_woh);   cudaGetSymbolAddress((void**)&wol,   g_wol);
    cudaGetSymbolAddress((void**)&l2h,   g_l2h);   cudaGetSymbolAddress((void**)&l2l,   g_l2l);
    cudaGetSymbolAddress((void**)&ffh,   g_ffh);   cudaGetSymbolAddress((void**)&ffl,   g_ffl);
    cudaGetSymbolAddress((void**)&w1f,   g_w1f);   cudaGetSymbolAddress((void**)&w2f,   g_w2f);

    const int gemm_smem = 2 * STAGE_B;    // 81920 B
    cudaFuncSetAttribute(gemm_mma<false>, cudaFuncAttributeMaxDynamicSharedMemorySize, gemm_smem);
    cudaFuncSetAttribute(gemm_mma<true >, cudaFuncAttributeMaxDynamicSharedMemorySize, gemm_smem);
    const int h2_smem = 2 * HSTAGE_B;     // 61440 B
    cudaFuncSetAttribute(gemm_h2<true,  true >, cudaFuncAttributeMaxDynamicSharedMemorySize, h2_smem);
    cudaFuncSetAttribute(gemm_h2<false, false>, cudaFuncAttributeMaxDynamicSharedMemorySize, h2_smem);
    const int attn_smem = 2 * ASTAGE;
    cudaFuncSetAttribute(attn_mma_kernel, cudaFuncAttributeMaxDynamicSharedMemorySize, attn_smem);

    dim3 wb(32, 8);
    dim3 gQKV (QKVW / BN, ROWS / BM);    // 24 x 32
    dim3 gProj(DMODEL / BN, ROWS / BM);  // 8 x 32
    dim3 gFF1 (FFDIM / BN, ROWS / BM);   // 32 x 32

    // launch 0: LN1 (bf16 split)
    ln_split_kernel<<<ROWS, 256>>>(x, g1, be1, lnh, lnl);
    // launch 1: fused QKV weight split (bf16)
    wsplit_qkv_kernel<<<dim3(DMODEL/32, DMODEL/32, 3), wb>>>(w_q, w_k, w_v, wqkvh, wqkvl);
    // launch 2: w_o split (bf16)
    wsplit_tr_kernel<<<dim3(DMODEL/32, DMODEL/32), wb>>>(w_o, woh, wol, DMODEL, DMODEL);
    // launch 3: fused QKV GEMM (bf16, profiled)
    gemm_mma<true><<<gQKV, 256, gemm_smem>>>(lnh, lnl, wqkvh, wqkvl, nullptr, nullptr, qkvh, qkvl, ROWS, QKVW, DMODEL);
    // FFN weight transposes (fp16)
    wtr_h_kernel<<<dim3(FFDIM/32,  DMODEL/32), wb>>>(w1, w1f, DMODEL, FFDIM);
    wtr_h_kernel<<<dim3(DMODEL/32, FFDIM/32),  wb>>>(w2, w2f, FFDIM, DMODEL);
    // V transpose (bf16)
    vtr_kernel<<<dim3(SEQ/32, 2, 32), wb>>>(qkvh, vth);
    vtr_kernel<<<dim3(SEQ/32, 2, 32), wb>>>(qkvl, vtl);
    // attention (bf16)
    attn_mma_kernel<<<dim3(SEQ/AQT, NHEAD, 2), 256, attn_smem>>>(qkvh, qkvl, vth, vtl, atth, attl);
    // output projection + residual (bf16 gemm, fp32 out)
    gemm_mma<false><<<gProj, 256, gemm_smem>>>(atth, attl, woh, wol, x, x1, nullptr, nullptr, ROWS, DMODEL, DMODEL);
    // LN2 -> fp16 split
    ln_split_h_kernel<<<ROWS, 256>>>(x1, g2, be2, l2h, l2l);
    // FFN (fp16 2-product)
    gemm_h2<true,  true ><<<gFF1,  256, h2_smem>>>(l2h, l2l, w1f, b1, nullptr, nullptr, ffh, ffl, ROWS, FFDIM, DMODEL);
    gemm_h2<false, false><<<gProj, 256, h2_smem>>>(ffh, ffl, w2f, b2, x1, out, nullptr, nullptr, ROWS, DMODEL, FFDIM);
}